// round 1
// baseline (speedup 1.0000x reference)
#include <cuda_runtime.h>
#include <math.h>

// ---------------------------------------------------------------------------
// Problem constants
// ---------------------------------------------------------------------------
#define BB    8
#define CIN   64
#define FS    512
#define H_IN  112
#define W_IN  112
#define HO    110
#define WO    110
#define NPOS  (BB * HO * WO)        // 96800 output positions
#define DEC   576                   // in_dim * 9
#define RED   128                   // out_dim
#define KTOT  576                   // conv K = 64*3*3

// Kernel 1 tiling (conv3x3 implicit GEMM)
#define K1_TP 32                    // positions per block (along ow)
#define K1_TF 128                   // filters per block
#define K1_KC 72                    // K chunk = 8 channels * 9 taps
#define K1_XS (CIN * 3 * 36)        // x patch floats (padded rows of 36)
#define K1_WS (K1_KC * 132)         // weight chunk floats (padded)
#define K1_SMEM ((K1_XS + K1_WS) * 4)

// Kernel 2 tiling (fused dec/red 1x1 GEMM)
#define K2_TP 64
#define K2_TN 64
#define K2_KC 64
#define NPT2 ((NPOS + K2_TP - 1) / K2_TP)   // 1513
#define NNT2 ((DEC + RED) / K2_TN)          // 11 (9 dec + 2 red)

// ---------------------------------------------------------------------------
// Device scratch (no cudaMalloc allowed)
// ---------------------------------------------------------------------------
__device__ float g_H[(size_t)NPOS * FS];     // ~198 MB hidden activations
__device__ float g_part[NPT2 * NNT2];        // per-block loss partial sums

// ---------------------------------------------------------------------------
// Kernel 1: h = relu(conv3x3(x, enc_w) + enc_b)  ->  g_H[p][f]
// ---------------------------------------------------------------------------
extern __shared__ float smem1[];

__global__ void __launch_bounds__(256, 3)
conv3x3_relu_kernel(const float* __restrict__ x,
                    const float* __restrict__ ew,
                    const float* __restrict__ eb)
{
    const int ftile = blockIdx.x;            // 0..3
    const int owt   = blockIdx.y;            // 0..3
    const int boh   = blockIdx.z;            // 0..879
    const int b  = boh / HO;
    const int oh = boh % HO;
    const int ow0    = owt * K1_TP;
    const int f_base = ftile * K1_TF;

    float* xs = smem1;               // [c][r][36], only cols 0..33 used
    float* ws = smem1 + K1_XS;       // [kk][132]  (transposed, f contiguous)

    const int tid = threadIdx.x;

    // ---- stage x patch: x[b, :, oh:oh+3, ow0:ow0+34] ----
    for (int idx = tid; idx < CIN * 3 * 34; idx += 256) {
        int c   = idx / 102;
        int rr  = idx % 102;
        int r   = rr / 34;
        int col = rr % 34;
        int ic  = ow0 + col;
        float v = 0.0f;
        if (ic < W_IN)
            v = x[((b * CIN + c) * H_IN + (oh + r)) * W_IN + ic];
        xs[(c * 3 + r) * 36 + col] = v;
    }

    const int pg = tid >> 5;          // 0..7  -> p0 = pg*4
    const int fg = tid & 31;          // 0..31 -> f0 = fg*4
    const int p0 = pg * 4;
    const int f0 = fg * 4;

    float acc[4][4];
#pragma unroll
    for (int i = 0; i < 4; ++i)
#pragma unroll
        for (int j = 0; j < 4; ++j) acc[i][j] = 0.0f;

    for (int chunk = 0; chunk < KTOT / K1_KC; ++chunk) {
        __syncthreads();   // protect ws reuse from previous chunk
        // stage weight chunk, transposed: ws[kk][f] = ew[f_base+f][chunk*72+kk]
        for (int idx = tid; idx < K1_TF * K1_KC; idx += 256) {
            int f  = idx / K1_KC;
            int kk = idx % K1_KC;
            ws[kk * 132 + f] = ew[(f_base + f) * KTOT + chunk * K1_KC + kk];
        }
        __syncthreads();

#pragma unroll
        for (int c8 = 0; c8 < 8; ++c8) {
            const int crow = (chunk * 8 + c8) * 3;
#pragma unroll
            for (int r = 0; r < 3; ++r) {
                const float* xr = &xs[(crow + r) * 36 + p0];
                float4 a4 = *(const float4*)xr;
                float2 a2 = *(const float2*)(xr + 4);
                float xv0 = a4.x, xv1 = a4.y, xv2 = a4.z;
                float xv3 = a4.w, xv4 = a2.x, xv5 = a2.y;
#pragma unroll
                for (int kw = 0; kw < 3; ++kw) {
                    const int k = c8 * 9 + r * 3 + kw;
                    float4 w4 = *(const float4*)&ws[k * 132 + f0];
                    float xa = (kw == 0) ? xv0 : (kw == 1) ? xv1 : xv2;
                    float xb = (kw == 0) ? xv1 : (kw == 1) ? xv2 : xv3;
                    float xc = (kw == 0) ? xv2 : (kw == 1) ? xv3 : xv4;
                    float xd = (kw == 0) ? xv3 : (kw == 1) ? xv4 : xv5;
                    acc[0][0] += xa * w4.x; acc[0][1] += xa * w4.y;
                    acc[0][2] += xa * w4.z; acc[0][3] += xa * w4.w;
                    acc[1][0] += xb * w4.x; acc[1][1] += xb * w4.y;
                    acc[1][2] += xb * w4.z; acc[1][3] += xb * w4.w;
                    acc[2][0] += xc * w4.x; acc[2][1] += xc * w4.y;
                    acc[2][2] += xc * w4.z; acc[2][3] += xc * w4.w;
                    acc[3][0] += xd * w4.x; acc[3][1] += xd * w4.y;
                    acc[3][2] += xd * w4.z; acc[3][3] += xd * w4.w;
                }
            }
        }
    }

    // ---- epilogue: bias + relu, write H ----
    float4 bias = *(const float4*)&eb[f_base + f0];
    const int Prow = (b * HO + oh) * WO;
#pragma unroll
    for (int i = 0; i < 4; ++i) {
        int ow = ow0 + p0 + i;
        if (ow < WO) {
            float4 hv;
            hv.x = fmaxf(acc[i][0] + bias.x, 0.0f);
            hv.y = fmaxf(acc[i][1] + bias.y, 0.0f);
            hv.z = fmaxf(acc[i][2] + bias.z, 0.0f);
            hv.w = fmaxf(acc[i][3] + bias.w, 0.0f);
            *(float4*)&g_H[(size_t)(Prow + ow) * FS + f_base + f0] = hv;
        }
    }
}

// ---------------------------------------------------------------------------
// Kernel 2: fused dec (sigmoid + MSE partials) and red (output) 1x1 convs
//   n-tiles 0..8  -> dec rows [ntile*64, +64)
//   n-tiles 9..10 -> red rows [(ntile-9)*64, +64)
// ---------------------------------------------------------------------------
__global__ void __launch_bounds__(256)
fc_fused_kernel(const float* __restrict__ x,
                const float* __restrict__ dw, const float* __restrict__ db,
                const float* __restrict__ rw, const float* __restrict__ rb,
                float* __restrict__ out)
{
    __shared__ float As[K2_KC * 68];   // [kk][p]
    __shared__ float Wt[K2_KC * 68];   // [kk][n]
    __shared__ float red_s[256];

    const int ntile = blockIdx.x;          // 0..10
    const int ptile = blockIdx.y;          // 0..1512
    const int P0 = ptile * K2_TP;
    const bool isdec = (ntile < 9);
    const float* wsrc = isdec ? dw : rw;
    const int n0g = isdec ? ntile * K2_TN : (ntile - 9) * K2_TN;

    const int tid = threadIdx.x;
    const int pg = tid >> 4, ng = tid & 15;
    const int p0 = pg * 4, n0 = ng * 4;

    float acc[4][4];
#pragma unroll
    for (int i = 0; i < 4; ++i)
#pragma unroll
        for (int j = 0; j < 4; ++j) acc[i][j] = 0.0f;

    for (int k0 = 0; k0 < FS; k0 += K2_KC) {
        __syncthreads();
        for (int idx = tid; idx < K2_TP * K2_KC; idx += 256) {
            int p  = idx >> 6;       // row index (p for A, n for W)
            int kk = idx & 63;
            int P  = P0 + p;
            As[kk * 68 + p] = (P < NPOS) ? g_H[(size_t)P * FS + k0 + kk] : 0.0f;
            Wt[kk * 68 + p] = wsrc[(n0g + p) * FS + k0 + kk];
        }
        __syncthreads();

#pragma unroll 16
        for (int kk = 0; kk < K2_KC; ++kk) {
            float4 av = *(const float4*)&As[kk * 68 + p0];
            float4 wv = *(const float4*)&Wt[kk * 68 + n0];
            acc[0][0] += av.x * wv.x; acc[0][1] += av.x * wv.y;
            acc[0][2] += av.x * wv.z; acc[0][3] += av.x * wv.w;
            acc[1][0] += av.y * wv.x; acc[1][1] += av.y * wv.y;
            acc[1][2] += av.y * wv.z; acc[1][3] += av.y * wv.w;
            acc[2][0] += av.z * wv.x; acc[2][1] += av.z * wv.y;
            acc[2][2] += av.z * wv.z; acc[2][3] += av.z * wv.w;
            acc[3][0] += av.w * wv.x; acc[3][1] += av.w * wv.y;
            acc[3][2] += av.w * wv.z; acc[3][3] += av.w * wv.w;
        }
    }

    float lsum = 0.0f;
    if (isdec) {
        const int dbase = n0g + n0;
        float4 dbv = *(const float4*)&db[dbase];
        float dbx[4] = {dbv.x, dbv.y, dbv.z, dbv.w};
#pragma unroll
        for (int i = 0; i < 4; ++i) {
            int P = P0 + p0 + i;
            if (P < NPOS) {
                int b  = P / (HO * WO);
                int r2 = P % (HO * WO);
                int oh = r2 / WO;
                int ow = r2 % WO;
#pragma unroll
                for (int j = 0; j < 4; ++j) {
                    int d   = dbase + j;
                    int c   = d / 9;
                    int rem = d - c * 9;
                    int kh  = rem / 3;
                    int kw  = rem - kh * 3;
                    float z   = acc[i][j] + dbx[j];
                    float aux = 1.0f / (1.0f + expf(-z));
                    float tgt = x[((b * CIN + c) * H_IN + oh + kh) * W_IN + ow + kw];
                    float df  = tgt - aux;
                    lsum += df * df;
                }
            }
        }
    } else {
        const int obase = n0g + n0;
        float4 rbv = *(const float4*)&rb[obase];
        float rbx[4] = {rbv.x, rbv.y, rbv.z, rbv.w};
#pragma unroll
        for (int i = 0; i < 4; ++i) {
            int P = P0 + p0 + i;
            if (P < NPOS) {
                int b  = P / (HO * WO);
                int r2 = P % (HO * WO);
#pragma unroll
                for (int j = 0; j < 4; ++j) {
                    int o = obase + j;
                    out[(b * RED + o) * (HO * WO) + r2] = acc[i][j] + rbx[j];
                }
            }
        }
    }

    // deterministic per-block loss reduction into fixed slot
    red_s[tid] = lsum;
    __syncthreads();
#pragma unroll
    for (int s = 128; s > 0; s >>= 1) {
        if (tid < s) red_s[tid] += red_s[tid + s];
        __syncthreads();
    }
    if (tid == 0) g_part[ptile * NNT2 + ntile] = red_s[0];
}

// ---------------------------------------------------------------------------
// Kernel 3: final loss reduction (double precision, fixed order -> deterministic)
// ---------------------------------------------------------------------------
__global__ void loss_reduce_kernel(float* __restrict__ out, int scalar_idx)
{
    __shared__ double s[256];
    double v = 0.0;
    for (int i = threadIdx.x; i < NPT2 * NNT2; i += 256)
        v += (double)g_part[i];
    s[threadIdx.x] = v;
    __syncthreads();
#pragma unroll
    for (int st = 128; st > 0; st >>= 1) {
        if (threadIdx.x < st) s[threadIdx.x] += s[threadIdx.x + st];
        __syncthreads();
    }
    if (threadIdx.x == 0)
        out[scalar_idx] = (float)(s[0] / (double)((size_t)NPOS * DEC));
}

// ---------------------------------------------------------------------------
// Launch
// ---------------------------------------------------------------------------
extern "C" void kernel_launch(void* const* d_in, const int* in_sizes, int n_in,
                              void* d_out, int out_size)
{
    const float* x    = (const float*)d_in[0];
    const float* ew   = (const float*)d_in[1];
    const float* eb   = (const float*)d_in[2];
    const float* dw   = (const float*)d_in[3];
    const float* db   = (const float*)d_in[4];
    const float* rw   = (const float*)d_in[5];
    const float* rb   = (const float*)d_in[6];
    float* out = (float*)d_out;

    static bool attr_set = false;
    if (!attr_set) {
        cudaFuncSetAttribute(conv3x3_relu_kernel,
                             cudaFuncAttributeMaxDynamicSharedMemorySize, K1_SMEM);
        attr_set = true;
    }

    // Kernel 1: conv3x3 + bias + relu -> g_H
    {
        dim3 grid(FS / K1_TF, (WO + K1_TP - 1) / K1_TP, BB * HO);  // (4, 4, 880)
        conv3x3_relu_kernel<<<grid, 256, K1_SMEM>>>(x, ew, eb);
    }

    // Kernel 2: fused dec/red GEMM + sigmoid/MSE partials + output write
    {
        dim3 grid(NNT2, NPT2);   // (11, 1513)
        fc_fused_kernel<<<grid, 256>>>(x, dw, db, rw, rb, out);
    }

    // Kernel 3: final loss scalar
    loss_reduce_kernel<<<1, 256>>>(out, out_size - 1);
}

// round 4
// speedup vs baseline: 1.8038x; 1.8038x over previous
#include <cuda_runtime.h>
#include <cuda_bf16.h>
#include <cstdint>
#include <math.h>

// ---------------------------------------------------------------------------
// Problem constants
// ---------------------------------------------------------------------------
#define BB    8
#define CIN   64
#define FS    512
#define HIN   112
#define WIN   112
#define HO    110
#define WO    110
#define NPOS  (BB * HO * WO)            // 96800
#define DEC   576
#define RED   128
#define KCONV 576

#define TM 128
#define TN 128
#define KCH 16                           // fp32 k per chunk

#define CONV_NCH (KCONV / KCH)           // 36
#define FC_NCH   (FS / KCH)              // 32
#define FC_MT    ((NPOS + TM - 1) / TM)  // 757
#define FC_NT    6                       // 768 virtual N
#define CONV_NT  (FS / TN)               // 4

// smem: per buffer A[128][32]bf16 (8KB) + B[128][32]bf16 (8KB)
#define BUFB   16384
#define ABOFF  8192

// ---------------------------------------------------------------------------
// Device scratch
// ---------------------------------------------------------------------------
__device__ float g_H[(size_t)NPOS * FS];       // ~198 MB
__device__ float g_part[FC_MT * FC_NT];

// ---------------------------------------------------------------------------
// helpers
// ---------------------------------------------------------------------------
__device__ __forceinline__ uint32_t smem_u32(const void* p) {
    uint32_t a;
    asm("{ .reg .u64 t; cvta.to.shared.u64 t, %1; cvt.u32.u64 %0, t; }"
        : "=r"(a) : "l"(p));
    return a;
}

// row pitch 64B (32 bf16); 16B chunk swizzle for conflict-free ldmatrix
__device__ __forceinline__ uint32_t tile_addr(uint32_t base, int row, int chunk) {
    return base + row * 64 + ((chunk ^ ((row >> 1) & 3)) << 4);
}

__device__ __forceinline__ void ldmx4(uint32_t* r, uint32_t addr) {
    asm volatile("ldmatrix.sync.aligned.m8n8.x4.shared.b16 {%0,%1,%2,%3}, [%4];"
                 : "=r"(r[0]), "=r"(r[1]), "=r"(r[2]), "=r"(r[3]) : "r"(addr));
}

__device__ __forceinline__ void mma_bf16(float* c, const uint32_t* a,
                                         uint32_t b0, uint32_t b1) {
    asm volatile("mma.sync.aligned.m16n8k16.row.col.f32.bf16.bf16.f32 "
                 "{%0,%1,%2,%3}, {%4,%5,%6,%7}, {%8,%9}, {%0,%1,%2,%3};"
                 : "+f"(c[0]), "+f"(c[1]), "+f"(c[2]), "+f"(c[3])
                 : "r"(a[0]), "r"(a[1]), "r"(a[2]), "r"(a[3]), "r"(b0), "r"(b1));
}

__device__ __forceinline__ void sts128(uint32_t addr, uint32_t a, uint32_t b,
                                       uint32_t c, uint32_t d) {
    asm volatile("st.shared.v4.b32 [%0], {%1,%2,%3,%4};"
                 :: "r"(addr), "r"(a), "r"(b), "r"(c), "r"(d) : "memory");
}

// split 8 fp32 -> hi/lo bf16 chunks, store 16B each
__device__ __forceinline__ void split_sts8(uint32_t base, int row, int chalf,
                                           const float* v) {
    uint32_t hw[4], lw[4];
#pragma unroll
    for (int q = 0; q < 4; ++q) {
        __nv_bfloat16 h0 = __float2bfloat16_rn(v[2 * q]);
        __nv_bfloat16 h1 = __float2bfloat16_rn(v[2 * q + 1]);
        float f0 = __bfloat162float(h0), f1 = __bfloat162float(h1);
        __nv_bfloat16 l0 = __float2bfloat16_rn(v[2 * q] - f0);
        __nv_bfloat16 l1 = __float2bfloat16_rn(v[2 * q + 1] - f1);
        hw[q] = (uint32_t)__bfloat16_as_ushort(h0) |
                ((uint32_t)__bfloat16_as_ushort(h1) << 16);
        lw[q] = (uint32_t)__bfloat16_as_ushort(l0) |
                ((uint32_t)__bfloat16_as_ushort(l1) << 16);
    }
    sts128(tile_addr(base, row, chalf), hw[0], hw[1], hw[2], hw[3]);
    sts128(tile_addr(base, row, 2 + chalf), lw[0], lw[1], lw[2], lw[3]);
}

// 3 split passes of mma over one staged chunk buffer
__device__ __forceinline__ void mma_passes(uint32_t Ab, uint32_t Bb, int lane,
                                           int m0w, int n0w, float acc[2][4][4]) {
#pragma unroll
    for (int ps = 0; ps < 3; ++ps) {
        const int ca = (ps == 2) ? 2 : 0;     // A: hi,hi,lo
        const int cb = (ps == 1) ? 2 : 0;     // B: hi,lo,hi
        uint32_t a[2][4], bq[2][4];
#pragma unroll
        for (int mi = 0; mi < 2; ++mi)
            ldmx4(a[mi], tile_addr(Ab, m0w + mi * 16 + (lane & 15),
                                   ca + (lane >> 4)));
#pragma unroll
        for (int nj2 = 0; nj2 < 2; ++nj2)
            ldmx4(bq[nj2], tile_addr(Bb, n0w + nj2 * 16 + (lane & 15),
                                     cb + (lane >> 4)));
#pragma unroll
        for (int mi = 0; mi < 2; ++mi) {
            mma_bf16(acc[mi][0], a[mi], bq[0][0], bq[0][2]);
            mma_bf16(acc[mi][1], a[mi], bq[0][1], bq[0][3]);
            mma_bf16(acc[mi][2], a[mi], bq[1][0], bq[1][2]);
            mma_bf16(acc[mi][3], a[mi], bq[1][1], bq[1][3]);
        }
    }
}

// ---------------------------------------------------------------------------
// Kernel 1: conv3x3 + bias + relu -> g_H.  M=ow(128 pad), N=filters(128)
// ---------------------------------------------------------------------------
__global__ void __launch_bounds__(512, 1)
conv_mma_kernel(const float* __restrict__ x,
                const float* __restrict__ ew,
                const float* __restrict__ eb)
{
    __shared__ alignas(1024) uint8_t smem[2 * BUFB];
    const uint32_t sb = smem_u32(smem);
    const int tid = threadIdx.x, lane = tid & 31, wid = tid >> 5;
    const int m0w = (wid >> 2) * 32, n0w = (wid & 3) * 32;
    const int ntile = blockIdx.x, boh = blockIdx.y;
    const int b = boh / HO, oh = boh % HO;
    const int fbase = ntile * TN;

    const bool isA = tid < 256;
    const int srow = (tid & 255) >> 1;      // 0..127
    const int chalf = tid & 1;

    float acc[2][4][4];
#pragma unroll
    for (int i = 0; i < 2; ++i)
#pragma unroll
        for (int j = 0; j < 4; ++j)
#pragma unroll
            for (int q = 0; q < 4; ++q) acc[i][j][q] = 0.f;

    // --- chunk loader: 8 fp32 into v ---
    auto load_chunk = [&](int ch, float* v) {
        const int k0 = ch * KCH + chalf * 8;
        if (isA) {
            if (srow < WO) {
#pragma unroll
                for (int j = 0; j < 8; ++j) {
                    const int kg = k0 + j;
                    const int c = kg / 9, t = kg - c * 9;
                    const int kh = t / 3, kw = t - kh * 3;
                    v[j] = x[(((size_t)b * CIN + c) * HIN + oh + kh) * WIN
                             + srow + kw];
                }
            } else {
#pragma unroll
                for (int j = 0; j < 8; ++j) v[j] = 0.f;
            }
        } else {
            const float4 q0 = *(const float4*)&ew[(size_t)(fbase + srow) * KCONV + k0];
            const float4 q1 = *(const float4*)&ew[(size_t)(fbase + srow) * KCONV + k0 + 4];
            v[0] = q0.x; v[1] = q0.y; v[2] = q0.z; v[3] = q0.w;
            v[4] = q1.x; v[5] = q1.y; v[6] = q1.z; v[7] = q1.w;
        }
    };

    // prologue: stage chunk 0
    {
        float v[8];
        load_chunk(0, v);
        split_sts8(sb + (isA ? 0 : ABOFF), srow, chalf, v);
    }

    for (int ch = 0; ch < CONV_NCH; ++ch) {
        __syncthreads();
        const bool nxt = (ch + 1 < CONV_NCH);
        float vn[8];
        if (nxt) load_chunk(ch + 1, vn);
        const uint32_t Ab = sb + (ch & 1) * BUFB;
        mma_passes(Ab, Ab + ABOFF, lane, m0w, n0w, acc);
        if (nxt)
            split_sts8(sb + ((ch + 1) & 1) * BUFB + (isA ? 0 : ABOFF),
                       srow, chalf, vn);
    }

    // epilogue: bias + relu -> g_H
    const int r0 = m0w + (lane >> 2);
#pragma unroll
    for (int mi = 0; mi < 2; ++mi) {
#pragma unroll
        for (int half = 0; half < 2; ++half) {
            const int ow = r0 + mi * 16 + half * 8;
            if (ow < WO) {
                const size_t rowoff = ((size_t)(b * HO + oh) * WO + ow) * FS;
#pragma unroll
                for (int nj = 0; nj < 4; ++nj) {
                    const int f = fbase + n0w + nj * 8 + (lane & 3) * 2;
                    float2 hv;
                    hv.x = fmaxf(acc[mi][nj][half * 2 + 0] + __ldg(&eb[f]), 0.f);
                    hv.y = fmaxf(acc[mi][nj][half * 2 + 1] + __ldg(&eb[f + 1]), 0.f);
                    *(float2*)&g_H[rowoff + f] = hv;
                }
            }
        }
    }
}

// ---------------------------------------------------------------------------
// Kernel 2: fused dec/red 1x1 GEMM.  M=positions(128), N=virtual cols(128)
//   virtual cols: [0,576) dec, [576,704) red, [704,768) pad
// ---------------------------------------------------------------------------
__global__ void __launch_bounds__(512, 1)
fc_mma_kernel(const float* __restrict__ x,
              const float* __restrict__ dw, const float* __restrict__ db,
              const float* __restrict__ rw, const float* __restrict__ rb,
              float* __restrict__ out)
{
    __shared__ alignas(1024) uint8_t smem[2 * BUFB];
    __shared__ float red_s[512];
    const uint32_t sb = smem_u32(smem);
    const int tid = threadIdx.x, lane = tid & 31, wid = tid >> 5;
    const int m0w = (wid >> 2) * 32, n0w = (wid & 3) * 32;
    const int nt = blockIdx.x, mt = blockIdx.y;
    const int P0 = mt * TM, N0 = nt * TN;

    const bool isA = tid < 256;
    const int srow = (tid & 255) >> 1;
    const int chalf = tid & 1;

    float acc[2][4][4];
#pragma unroll
    for (int i = 0; i < 2; ++i)
#pragma unroll
        for (int j = 0; j < 4; ++j)
#pragma unroll
            for (int q = 0; q < 4; ++q) acc[i][j][q] = 0.f;

    auto load_chunk = [&](int ch, float* v) {
        const int k0 = ch * KCH + chalf * 8;
        if (isA) {
            const int P = P0 + srow;
            if (P < NPOS) {
                const float4 q0 = *(const float4*)&g_H[(size_t)P * FS + k0];
                const float4 q1 = *(const float4*)&g_H[(size_t)P * FS + k0 + 4];
                v[0] = q0.x; v[1] = q0.y; v[2] = q0.z; v[3] = q0.w;
                v[4] = q1.x; v[5] = q1.y; v[6] = q1.z; v[7] = q1.w;
            } else {
#pragma unroll
                for (int j = 0; j < 8; ++j) v[j] = 0.f;
            }
        } else {
            const int ng = N0 + srow;
            const float* src = nullptr;
            if (ng < DEC)            src = &dw[(size_t)ng * FS + k0];
            else if (ng < DEC + RED) src = &rw[(size_t)(ng - DEC) * FS + k0];
            if (src) {
                const float4 q0 = *(const float4*)src;
                const float4 q1 = *(const float4*)(src + 4);
                v[0] = q0.x; v[1] = q0.y; v[2] = q0.z; v[3] = q0.w;
                v[4] = q1.x; v[5] = q1.y; v[6] = q1.z; v[7] = q1.w;
            } else {
#pragma unroll
                for (int j = 0; j < 8; ++j) v[j] = 0.f;
            }
        }
    };

    {
        float v[8];
        load_chunk(0, v);
        split_sts8(sb + (isA ? 0 : ABOFF), srow, chalf, v);
    }

    for (int ch = 0; ch < FC_NCH; ++ch) {
        __syncthreads();
        const bool nxt = (ch + 1 < FC_NCH);
        float vn[8];
        if (nxt) load_chunk(ch + 1, vn);
        const uint32_t Ab = sb + (ch & 1) * BUFB;
        mma_passes(Ab, Ab + ABOFF, lane, m0w, n0w, acc);
        if (nxt)
            split_sts8(sb + ((ch + 1) & 1) * BUFB + (isA ? 0 : ABOFF),
                       srow, chalf, vn);
    }

    // ---- epilogue: dec -> sigmoid/MSE partial, red -> output ----
    float lsum = 0.f;
#pragma unroll
    for (int mi = 0; mi < 2; ++mi) {
#pragma unroll
        for (int half = 0; half < 2; ++half) {
            const int m = m0w + mi * 16 + half * 8 + (lane >> 2);
            const int P = P0 + m;
            if (P < NPOS) {
                const int bb = P / (HO * WO);
                const int r2 = P - bb * (HO * WO);
                const int ohh = r2 / WO;
                const int oww = r2 - ohh * WO;
#pragma unroll
                for (int nj = 0; nj < 4; ++nj) {
#pragma unroll
                    for (int e = 0; e < 2; ++e) {
                        const int ng = N0 + n0w + nj * 8 + (lane & 3) * 2 + e;
                        const float val = acc[mi][nj][half * 2 + e];
                        if (ng < DEC) {
                            const int c = ng / 9, t = ng - c * 9;
                            const int kh = t / 3, kw = t - kh * 3;
                            const float z = val + __ldg(&db[ng]);
                            const float aux = 1.f / (1.f + expf(-z));
                            const float tg = x[(((size_t)bb * CIN + c) * HIN
                                               + ohh + kh) * WIN + oww + kw];
                            const float df = tg - aux;
                            lsum += df * df;
                        } else if (ng < DEC + RED) {
                            const int o = ng - DEC;
                            out[((size_t)bb * RED + o) * (HO * WO) + r2] =
                                val + __ldg(&rb[o]);
                        }
                    }
                }
            }
        }
    }

    __syncthreads();                // smem (aliased by ldmatrix) now safe
    red_s[tid] = lsum;
    __syncthreads();
#pragma unroll
    for (int s = 256; s > 0; s >>= 1) {
        if (tid < s) red_s[tid] += red_s[tid + s];
        __syncthreads();
    }
    if (tid == 0) g_part[mt * FC_NT + nt] = red_s[0];
}

// ---------------------------------------------------------------------------
// Kernel 3: final loss scalar (deterministic, double accumulation)
// ---------------------------------------------------------------------------
__global__ void loss_reduce_kernel(float* __restrict__ out, int scalar_idx)
{
    __shared__ double s[256];
    double v = 0.0;
    for (int i = threadIdx.x; i < FC_MT * FC_NT; i += 256)
        v += (double)g_part[i];
    s[threadIdx.x] = v;
    __syncthreads();
#pragma unroll
    for (int st = 128; st > 0; st >>= 1) {
        if (threadIdx.x < st) s[threadIdx.x] += s[threadIdx.x + st];
        __syncthreads();
    }
    if (threadIdx.x == 0)
        out[scalar_idx] = (float)(s[0] / (double)((size_t)NPOS * DEC));
}

// ---------------------------------------------------------------------------
// Launch
// ---------------------------------------------------------------------------
extern "C" void kernel_launch(void* const* d_in, const int* in_sizes, int n_in,
                              void* d_out, int out_size)
{
    const float* x  = (const float*)d_in[0];
    const float* ew = (const float*)d_in[1];
    const float* eb = (const float*)d_in[2];
    const float* dw = (const float*)d_in[3];
    const float* db = (const float*)d_in[4];
    const float* rw = (const float*)d_in[5];
    const float* rb = (const float*)d_in[6];
    float* out = (float*)d_out;

    {   // conv3x3 -> H
        dim3 grid(CONV_NT, BB * HO);            // (4, 880)
        conv_mma_kernel<<<grid, 512>>>(x, ew, eb);
    }
    {   // fused dec/red GEMM + epilogues
        dim3 grid(FC_NT, FC_MT);                // (6, 757)
        fc_mma_kernel<<<grid, 512>>>(x, dw, db, rw, rb, out);
    }
    loss_reduce_kernel<<<1, 256>>>(out, out_size - 1);
}

// round 5
// speedup vs baseline: 2.6825x; 1.4871x over previous
#include <cuda_runtime.h>
#include <cuda_bf16.h>
#include <cstdint>
#include <math.h>

// ---------------------------------------------------------------------------
// Problem constants
// ---------------------------------------------------------------------------
#define BB    8
#define CIN   64
#define FS    512
#define HIN   112
#define WIN   112
#define WPAD  128
#define HO    110
#define WO    110
#define NPOS  (BB * HO * WO)            // 96800
#define NPOSP (757 * 128)               // 96896 padded
#define DEC   576
#define RED   128
#define KCONV 576
#define NV    768                       // virtual N for fc (dec+red+pad)

#define TM 128
#define TN 256
#define KC 16

#define K1_NCH (KCONV / KC)             // 36
#define K2_NCH (FS / KC)                // 32
#define K2_MT  757
#define K2_NT  3

#define NSTAGE 4
#define STAGE_BYTES 24576               // A 8KB + B 16KB
#define SM_B   8192
#define SMEM_TOTAL (NSTAGE * STAGE_BYTES)   // 98304

// ---------------------------------------------------------------------------
// Device scratch (bf16 hi/lo pre-split)
// ---------------------------------------------------------------------------
__device__ __nv_bfloat16 g_xh[(size_t)3 * BB * CIN * HIN * WPAD];   // 44 MB
__device__ __nv_bfloat16 g_xl[(size_t)3 * BB * CIN * HIN * WPAD];
__device__ __nv_bfloat16 g_ewh[FS * KCONV];
__device__ __nv_bfloat16 g_ewl[FS * KCONV];
__device__ __nv_bfloat16 g_w2h[NV * FS];
__device__ __nv_bfloat16 g_w2l[NV * FS];
__device__ __nv_bfloat16 g_hh[(size_t)NPOSP * FS];                  // 99 MB
__device__ __nv_bfloat16 g_hl[(size_t)NPOSP * FS];
__device__ float g_part[K2_MT * K2_NT];

// ---------------------------------------------------------------------------
// helpers
// ---------------------------------------------------------------------------
__device__ __forceinline__ uint32_t smem_u32(const void* p) {
    uint32_t a;
    asm("{ .reg .u64 t; cvta.to.shared.u64 t, %1; cvt.u32.u64 %0, t; }"
        : "=r"(a) : "l"(p));
    return a;
}
__device__ __forceinline__ void cpa16(uint32_t dst, const void* src) {
    asm volatile("cp.async.cg.shared.global [%0], [%1], 16;"
                 :: "r"(dst), "l"(src));
}
#define CP_COMMIT() asm volatile("cp.async.commit_group;" ::: "memory")
#define CP_WAIT2()  asm volatile("cp.async.wait_group 2;" ::: "memory")

__device__ __forceinline__ void ldmx4(uint32_t* r, uint32_t addr) {
    asm volatile("ldmatrix.sync.aligned.m8n8.x4.shared.b16 {%0,%1,%2,%3}, [%4];"
                 : "=r"(r[0]), "=r"(r[1]), "=r"(r[2]), "=r"(r[3]) : "r"(addr));
}
__device__ __forceinline__ void ldmx4t(uint32_t* r, uint32_t addr) {
    asm volatile("ldmatrix.sync.aligned.m8n8.x4.trans.shared.b16 {%0,%1,%2,%3}, [%4];"
                 : "=r"(r[0]), "=r"(r[1]), "=r"(r[2]), "=r"(r[3]) : "r"(addr));
}
__device__ __forceinline__ void mma_bf16(float* c, const uint32_t* a,
                                         uint32_t b0, uint32_t b1) {
    asm volatile("mma.sync.aligned.m16n8k16.row.col.f32.bf16.bf16.f32 "
                 "{%0,%1,%2,%3}, {%4,%5,%6,%7}, {%8,%9}, {%0,%1,%2,%3};"
                 : "+f"(c[0]), "+f"(c[1]), "+f"(c[2]), "+f"(c[3])
                 : "r"(a[0]), "r"(a[1]), "r"(a[2]), "r"(a[3]), "r"(b0), "r"(b1));
}

// A fragment from [k16][m128] tile (256B pitch, chunk^(k&7) swizzle), transposed
__device__ __forceinline__ void lda_t(uint32_t* a, uint32_t base, int m0, int lane) {
    const int kk  = (lane & 7) | ((lane >> 4) << 3);
    const int mch = (m0 >> 3) + ((lane >> 3) & 1);
    ldmx4t(a, base + kk * 256 + ((mch ^ (kk & 7)) << 4));
}
// A fragment from [m128][64B] tile (R4 layout), non-transposed. ca: 0=hi, 2=lo
__device__ __forceinline__ void lda_n(uint32_t* a, uint32_t base, int ca,
                                      int m0, int lane) {
    const int row = m0 + (lane & 15);
    ldmx4(a, base + row * 64 + (((ca + (lane >> 4)) ^ ((row >> 1) & 3)) << 4));
}

// One pass over 64 n-columns for this warp. cb: 0 = B hi, 2 = B lo.
__device__ __forceinline__ void mma_pass(uint32_t Bst, int cb,
                                         const uint32_t* a0, const uint32_t* a1,
                                         int n0w, int lane, float acc[2][8][4]) {
#pragma unroll
    for (int g = 0; g < 4; ++g) {
        const int row = n0w + g * 16 + (lane & 15);
        uint32_t bq[4];
        ldmx4(bq, Bst + row * 64 + (((cb + (lane >> 4)) ^ ((row >> 1) & 3)) << 4));
        mma_bf16(acc[0][2 * g],     a0, bq[0], bq[2]);
        mma_bf16(acc[0][2 * g + 1], a0, bq[1], bq[3]);
        mma_bf16(acc[1][2 * g],     a1, bq[0], bq[2]);
        mma_bf16(acc[1][2 * g + 1], a1, bq[1], bq[3]);
    }
}

__device__ __forceinline__ void split2(float v, __nv_bfloat16& h, __nv_bfloat16& l) {
    h = __float2bfloat16_rn(v);
    l = __float2bfloat16_rn(v - __bfloat162float(h));
}

// ---------------------------------------------------------------------------
// Prep kernels: pre-split to bf16 hi/lo
// ---------------------------------------------------------------------------
__global__ void prep_x_kernel(const float* __restrict__ x)
{
    const size_t idx = (size_t)blockIdx.x * 512 + threadIdx.x;
    if (idx >= (size_t)3 * BB * CIN * HIN * WPAD) return;
    const int w = idx & 127;
    size_t r = idx >> 7;
    const int h = r % HIN;  r /= HIN;
    const int c = r & 63;   r >>= 6;
    const int b = r & 7;
    const int kw = (int)(r >> 3);
    float v = 0.f;
    if (w + kw < WIN)
        v = x[(((size_t)b * CIN + c) * HIN + h) * WIN + w + kw];
    __nv_bfloat16 hi, lo; split2(v, hi, lo);
    g_xh[idx] = hi; g_xl[idx] = lo;
}

__global__ void prep_w_kernel(const float* __restrict__ ew,
                              const float* __restrict__ dw,
                              const float* __restrict__ rw)
{
    const int idx = blockIdx.x * 512 + threadIdx.x;
    if (idx < FS * KCONV) {
        __nv_bfloat16 hi, lo; split2(ew[idx], hi, lo);
        g_ewh[idx] = hi; g_ewl[idx] = lo;
    }
    const int j = idx - FS * KCONV;
    if (j >= 0 && j < NV * FS) {
        const int n = j >> 9, k = j & 511;
        float v = 0.f;
        if (n < DEC)            v = dw[n * FS + k];
        else if (n < DEC + RED) v = rw[(n - DEC) * FS + k];
        __nv_bfloat16 hi, lo; split2(v, hi, lo);
        g_w2h[j] = hi; g_w2l[j] = lo;
    }
}

// ---------------------------------------------------------------------------
// Kernel 1: conv3x3 + bias + relu -> g_hh/g_hl.  M=ow(128), N=filters(256)
// A staged [k][m] (trans), 3-pass bf16 split, cp.async 4-stage pipeline.
// ---------------------------------------------------------------------------
__global__ void __launch_bounds__(512, 1)
conv_mma_kernel(const float* __restrict__ eb)
{
    extern __shared__ uint8_t smem[];
    const uint32_t sb = smem_u32(smem);
    const int tid = threadIdx.x, lane = tid & 31, wid = tid >> 5;
    const int m0w = (wid >> 2) * 32, n0w = (wid & 3) * 64;
    const int ftile = blockIdx.x, boh = blockIdx.y;
    const int b = boh / HO, oh = boh % HO;
    const int fbase = ftile * TN;

    // per-thread invariant staging roles
    const int ar = tid >> 4, acq = tid & 15;
    const int ahalf = ar >> 4, akr = ar & 15;

    auto issue_stage = [&](int slot, int ch) {
        const uint32_t st = sb + slot * STAGE_BYTES;
        const int k0 = ch * KC;
        {   // A: 32 rows (hi 0-15, lo 16-31) x 16 chunks = 512 ops
            const int k = k0 + akr;
            const int c = k / 9, t = k - c * 9, kh = t / 3, kw = t - kh * 3;
            const __nv_bfloat16* src = (ahalf ? g_xl : g_xh)
                + (((((size_t)kw * BB + b) * CIN + c) * HIN + oh + kh) << 7)
                + (acq << 3);
            cpa16(st + ahalf * 4096 + akr * 256 + ((acq ^ (akr & 7)) << 4), src);
        }
#pragma unroll
        for (int s = 0; s < 2; ++s) {   // B: 256 rows x 4 chunks = 1024 ops
            const int idx = tid + (s << 9);
            const int n = idx >> 2, cq = idx & 3;
            const __nv_bfloat16* src = (cq < 2 ? g_ewh : g_ewl)
                + (size_t)(fbase + n) * KCONV + k0 + ((cq & 1) << 3);
            cpa16(st + SM_B + n * 64 + ((cq ^ ((n >> 1) & 3)) << 4), src);
        }
    };

    float acc[2][8][4];
#pragma unroll
    for (int i = 0; i < 2; ++i)
#pragma unroll
        for (int j = 0; j < 8; ++j)
#pragma unroll
            for (int q = 0; q < 4; ++q) acc[i][j][q] = 0.f;

    for (int s = 0; s < NSTAGE - 1; ++s) { issue_stage(s, s); CP_COMMIT(); }

    for (int ch = 0; ch < K1_NCH; ++ch) {
        CP_WAIT2();
        __syncthreads();
        const int nc = ch + NSTAGE - 1;
        if (nc < K1_NCH) issue_stage(nc & (NSTAGE - 1), nc);
        CP_COMMIT();

        const uint32_t st = sb + (ch & (NSTAGE - 1)) * STAGE_BYTES;
        uint32_t a0[4], a1[4];
        lda_t(a0, st, m0w, lane);
        lda_t(a1, st, m0w + 16, lane);
        mma_pass(st + SM_B, 0, a0, a1, n0w, lane, acc);   // Ah*Bh
        mma_pass(st + SM_B, 2, a0, a1, n0w, lane, acc);   // Ah*Bl
        lda_t(a0, st + 4096, m0w, lane);
        lda_t(a1, st + 4096, m0w + 16, lane);
        mma_pass(st + SM_B, 0, a0, a1, n0w, lane, acc);   // Al*Bh
    }

    // epilogue: bias + relu, split hi/lo, write g_hh/g_hl [P][f]
    float ebv[16];
#pragma unroll
    for (int nj = 0; nj < 8; ++nj) {
        const int f = fbase + n0w + nj * 8 + (lane & 3) * 2;
        ebv[2 * nj]     = __ldg(&eb[f]);
        ebv[2 * nj + 1] = __ldg(&eb[f + 1]);
    }
#pragma unroll
    for (int mi = 0; mi < 2; ++mi) {
#pragma unroll
        for (int half = 0; half < 2; ++half) {
            const int ow = m0w + mi * 16 + half * 8 + (lane >> 2);
            if (ow < WO) {
                const size_t base = (size_t)((b * HO + oh) * WO + ow) * FS;
#pragma unroll
                for (int nj = 0; nj < 8; ++nj) {
                    const int f = fbase + n0w + nj * 8 + (lane & 3) * 2;
                    const float v0 = fmaxf(acc[mi][nj][half * 2 + 0] + ebv[2 * nj], 0.f);
                    const float v1 = fmaxf(acc[mi][nj][half * 2 + 1] + ebv[2 * nj + 1], 0.f);
                    __nv_bfloat16 h0, l0, h1, l1;
                    split2(v0, h0, l0); split2(v1, h1, l1);
                    const uint32_t ph = (uint32_t)__bfloat16_as_ushort(h0) |
                                        ((uint32_t)__bfloat16_as_ushort(h1) << 16);
                    const uint32_t pl = (uint32_t)__bfloat16_as_ushort(l0) |
                                        ((uint32_t)__bfloat16_as_ushort(l1) << 16);
                    *(uint32_t*)&g_hh[base + f] = ph;
                    *(uint32_t*)&g_hl[base + f] = pl;
                }
            }
        }
    }
}

// ---------------------------------------------------------------------------
// Kernel 2: fused dec/red 1x1 GEMM.  M=128 positions, N=256 virtual cols.
// NPASS=1: pure-dec tiles (bf16 hi only). NPASS=3: mixed dec/red tile.
// ---------------------------------------------------------------------------
template <int NPASS>
__global__ void __launch_bounds__(512, 1)
fc_mma_kernel(const float* __restrict__ x,
              const float* __restrict__ db, const float* __restrict__ rb,
              float* __restrict__ out, int ntbase)
{
    extern __shared__ uint8_t smem[];
    const uint32_t sb = smem_u32(smem);
    const int tid = threadIdx.x, lane = tid & 31, wid = tid >> 5;
    const int m0w = (wid >> 2) * 32, n0w = (wid & 3) * 64;
    const int nt = ntbase + blockIdx.x, mt = blockIdx.y;
    const int P0 = mt * TM, N0 = nt * TN;

    auto issue_stage = [&](int slot, int ch) {
        const uint32_t st = sb + slot * STAGE_BYTES;
        const int k0 = ch * KC;
        const int nA   = (NPASS == 1) ? 256 : 512;
        const int nops = (NPASS == 1) ? 768 : 1536;
        for (int i = tid; i < nops; i += 512) {
            if (i < nA) {
                int m, cq; const __nv_bfloat16* g;
                if (NPASS == 1) { m = i >> 1; cq = i & 1; g = g_hh; }
                else            { m = i >> 2; cq = i & 3; g = (cq < 2) ? g_hh : g_hl; }
                const __nv_bfloat16* src = g + (size_t)(P0 + m) * FS + k0 + ((cq & 1) << 3);
                cpa16(st + m * 64 + ((cq ^ ((m >> 1) & 3)) << 4), src);
            } else {
                const int j = i - nA;
                int n, cq; const __nv_bfloat16* g;
                if (NPASS == 1) { n = j >> 1; cq = j & 1; g = g_w2h; }
                else            { n = j >> 2; cq = j & 3; g = (cq < 2) ? g_w2h : g_w2l; }
                const __nv_bfloat16* src = g + (size_t)(N0 + n) * FS + k0 + ((cq & 1) << 3);
                cpa16(st + SM_B + n * 64 + ((cq ^ ((n >> 1) & 3)) << 4), src);
            }
        }
    };

    float acc[2][8][4];
#pragma unroll
    for (int i = 0; i < 2; ++i)
#pragma unroll
        for (int j = 0; j < 8; ++j)
#pragma unroll
            for (int q = 0; q < 4; ++q) acc[i][j][q] = 0.f;

    for (int s = 0; s < NSTAGE - 1; ++s) { issue_stage(s, s); CP_COMMIT(); }

    for (int ch = 0; ch < K2_NCH; ++ch) {
        CP_WAIT2();
        __syncthreads();
        const int nc = ch + NSTAGE - 1;
        if (nc < K2_NCH) issue_stage(nc & (NSTAGE - 1), nc);
        CP_COMMIT();

        const uint32_t st = sb + (ch & (NSTAGE - 1)) * STAGE_BYTES;
        uint32_t a0[4], a1[4];
        lda_n(a0, st, 0, m0w, lane);
        lda_n(a1, st, 0, m0w + 16, lane);
        mma_pass(st + SM_B, 0, a0, a1, n0w, lane, acc);       // Ah*Bh
        if (NPASS == 3) {
            mma_pass(st + SM_B, 2, a0, a1, n0w, lane, acc);   // Ah*Bl
            lda_n(a0, st, 2, m0w, lane);
            lda_n(a1, st, 2, m0w + 16, lane);
            mma_pass(st + SM_B, 0, a0, a1, n0w, lane, acc);   // Al*Bh
        }
    }

    // ---- epilogue: dec -> sigmoid/MSE partial, red -> output ----
    float lsum = 0.f;
#pragma unroll
    for (int mi = 0; mi < 2; ++mi) {
#pragma unroll
        for (int half = 0; half < 2; ++half) {
            const int m = m0w + mi * 16 + half * 8 + (lane >> 2);
            const int P = P0 + m;
            if (P < NPOS) {
                const int bb = P / (HO * WO);
                const int r2 = P - bb * (HO * WO);
                const int ohh = r2 / WO;
                const int oww = r2 - ohh * WO;
#pragma unroll
                for (int nj = 0; nj < 8; ++nj) {
#pragma unroll
                    for (int e = 0; e < 2; ++e) {
                        const int ng = N0 + n0w + nj * 8 + (lane & 3) * 2 + e;
                        const float val = acc[mi][nj][half * 2 + e];
                        if (ng < DEC) {
                            const int c = ng / 9, t = ng - c * 9;
                            const int kh = t / 3, kw = t - kh * 3;
                            const float z = val + __ldg(&db[ng]);
                            const float aux = 1.f / (1.f + expf(-z));
                            const float tg = x[(((size_t)bb * CIN + c) * HIN
                                               + ohh + kh) * WIN + oww + kw];
                            const float df = tg - aux;
                            lsum += df * df;
                        } else if (ng < DEC + RED) {
                            const int o = ng - DEC;
                            out[((size_t)bb * RED + o) * (HO * WO) + r2] =
                                val + __ldg(&rb[o]);
                        }
                    }
                }
            }
        }
    }

    __syncthreads();
    float* red_s = (float*)smem;
    red_s[tid] = lsum;
    __syncthreads();
#pragma unroll
    for (int s = 256; s > 0; s >>= 1) {
        if (tid < s) red_s[tid] += red_s[tid + s];
        __syncthreads();
    }
    if (tid == 0) g_part[mt * K2_NT + nt] = red_s[0];
}

// ---------------------------------------------------------------------------
// Kernel 3: final loss scalar (deterministic double accumulation)
// ---------------------------------------------------------------------------
__global__ void loss_reduce_kernel(float* __restrict__ out, int scalar_idx)
{
    __shared__ double s[256];
    double v = 0.0;
    for (int i = threadIdx.x; i < K2_MT * K2_NT; i += 256)
        v += (double)g_part[i];
    s[threadIdx.x] = v;
    __syncthreads();
#pragma unroll
    for (int st = 128; st > 0; st >>= 1) {
        if (threadIdx.x < st) s[threadIdx.x] += s[threadIdx.x + st];
        __syncthreads();
    }
    if (threadIdx.x == 0)
        out[scalar_idx] = (float)(s[0] / (double)((size_t)NPOS * DEC));
}

// ---------------------------------------------------------------------------
// Launch
// ---------------------------------------------------------------------------
extern "C" void kernel_launch(void* const* d_in, const int* in_sizes, int n_in,
                              void* d_out, int out_size)
{
    const float* x  = (const float*)d_in[0];
    const float* ew = (const float*)d_in[1];
    const float* eb = (const float*)d_in[2];
    const float* dw = (const float*)d_in[3];
    const float* db = (const float*)d_in[4];
    const float* rw = (const float*)d_in[5];
    const float* rb = (const float*)d_in[6];
    float* out = (float*)d_out;

    static bool attr_set = false;
    if (!attr_set) {
        cudaFuncSetAttribute(conv_mma_kernel,
                             cudaFuncAttributeMaxDynamicSharedMemorySize, SMEM_TOTAL);
        cudaFuncSetAttribute(fc_mma_kernel<1>,
                             cudaFuncAttributeMaxDynamicSharedMemorySize, SMEM_TOTAL);
        cudaFuncSetAttribute(fc_mma_kernel<3>,
                             cudaFuncAttributeMaxDynamicSharedMemorySize, SMEM_TOTAL);
        attr_set = true;
    }

    {   // pre-split inputs to bf16 hi/lo
        const size_t nx = (size_t)3 * BB * CIN * HIN * WPAD;
        prep_x_kernel<<<(unsigned)((nx + 511) / 512), 512>>>(x);
        const int nw = FS * KCONV + NV * FS;
        prep_w_kernel<<<(nw + 511) / 512, 512>>>(ew, dw, rw);
    }
    {   // conv3x3 -> H (bf16 hi/lo)
        dim3 grid(FS / TN, BB * HO);                 // (2, 880)
        conv_mma_kernel<<<grid, 512, SMEM_TOTAL>>>(eb);
    }
    {   // fc: pure-dec tiles (1-pass) and mixed dec/red tile (3-pass)
        dim3 grid_a(2, K2_MT);
        fc_mma_kernel<1><<<grid_a, 512, SMEM_TOTAL>>>(x, db, rb, out, 0);
        dim3 grid_b(1, K2_MT);
        fc_mma_kernel<3><<<grid_b, 512, SMEM_TOTAL>>>(x, db, rb, out, 2);
    }
    loss_reduce_kernel<<<1, 256>>>(out, out_size - 1);
}

// round 6
// speedup vs baseline: 2.7442x; 1.0230x over previous
#include <cuda_runtime.h>
#include <cuda_bf16.h>
#include <cstdint>
#include <math.h>

// ---------------------------------------------------------------------------
// Problem constants
// ---------------------------------------------------------------------------
#define BB    8
#define CIN   64
#define FS    512
#define HIN   112
#define WIN   112
#define WPAD  128
#define HO    110
#define WO    110
#define NPOS  (BB * HO * WO)            // 96800
#define NPOSP (757 * 128)               // 96896 padded
#define DEC   576
#define RED   128
#define KCONV 576
#define NV    768                       // virtual N for fc (dec+red+pad)

#define TM 128
#define TN 256
#define KC 16

#define K1_NCH (KCONV / KC)             // 36
#define K2_NCH (FS / KC)                // 32
#define K2_MT  757
#define K2_NT  3

#define NSTAGE 6
#define STAGE_BYTES 24576               // A 8KB + B 16KB
#define SM_B   8192
#define SMEM_TOTAL (NSTAGE * STAGE_BYTES)   // 147456

// ---------------------------------------------------------------------------
// Device scratch (bf16 hi/lo pre-split)
// ---------------------------------------------------------------------------
__device__ __nv_bfloat16 g_xh[(size_t)3 * BB * CIN * HIN * WPAD];   // 44 MB
__device__ __nv_bfloat16 g_xl[(size_t)3 * BB * CIN * HIN * WPAD];
__device__ __nv_bfloat16 g_ewh[FS * KCONV];
__device__ __nv_bfloat16 g_ewl[FS * KCONV];
__device__ __nv_bfloat16 g_w2h[NV * FS];
__device__ __nv_bfloat16 g_w2l[NV * FS];
__device__ __nv_bfloat16 g_hh[(size_t)NPOSP * FS];                  // 99 MB
__device__ __nv_bfloat16 g_hl[(size_t)NPOSP * FS];
__device__ float g_part[K2_MT * K2_NT];

// ---------------------------------------------------------------------------
// helpers
// ---------------------------------------------------------------------------
__device__ __forceinline__ uint32_t smem_u32(const void* p) {
    uint32_t a;
    asm("{ .reg .u64 t; cvta.to.shared.u64 t, %1; cvt.u32.u64 %0, t; }"
        : "=r"(a) : "l"(p));
    return a;
}
__device__ __forceinline__ void cpa16(uint32_t dst, const void* src) {
    asm volatile("cp.async.cg.shared.global [%0], [%1], 16;"
                 :: "r"(dst), "l"(src));
}
#define CP_COMMIT() asm volatile("cp.async.commit_group;" ::: "memory")
#define CP_WAIT2()  asm volatile("cp.async.wait_group 2;" ::: "memory")

__device__ __forceinline__ void ldmx4(uint32_t* r, uint32_t addr) {
    asm volatile("ldmatrix.sync.aligned.m8n8.x4.shared.b16 {%0,%1,%2,%3}, [%4];"
                 : "=r"(r[0]), "=r"(r[1]), "=r"(r[2]), "=r"(r[3]) : "r"(addr));
}
__device__ __forceinline__ void ldmx4t(uint32_t* r, uint32_t addr) {
    asm volatile("ldmatrix.sync.aligned.m8n8.x4.trans.shared.b16 {%0,%1,%2,%3}, [%4];"
                 : "=r"(r[0]), "=r"(r[1]), "=r"(r[2]), "=r"(r[3]) : "r"(addr));
}
__device__ __forceinline__ void mma_bf16(float* c, const uint32_t* a,
                                         uint32_t b0, uint32_t b1) {
    asm volatile("mma.sync.aligned.m16n8k16.row.col.f32.bf16.bf16.f32 "
                 "{%0,%1,%2,%3}, {%4,%5,%6,%7}, {%8,%9}, {%0,%1,%2,%3};"
                 : "+f"(c[0]), "+f"(c[1]), "+f"(c[2]), "+f"(c[3])
                 : "r"(a[0]), "r"(a[1]), "r"(a[2]), "r"(a[3]), "r"(b0), "r"(b1));
}

// A fragment from [k16][m128] tile (256B pitch, chunk^(k&7) swizzle), transposed
__device__ __forceinline__ void lda_t(uint32_t* a, uint32_t base, int m0, int lane) {
    const int kk  = (lane & 7) | ((lane >> 4) << 3);
    const int mch = (m0 >> 3) + ((lane >> 3) & 1);
    ldmx4t(a, base + kk * 256 + ((mch ^ (kk & 7)) << 4));
}
// A fragment from [m128][64B] tile, non-transposed. ca: 0=hi, 2=lo
__device__ __forceinline__ void lda_n(uint32_t* a, uint32_t base, int ca,
                                      int m0, int lane) {
    const int row = m0 + (lane & 15);
    ldmx4(a, base + row * 64 + (((ca + (lane >> 4)) ^ ((row >> 1) & 3)) << 4));
}

// One pass over 64 n-columns for this warp. cb: 0 = B hi, 2 = B lo.
__device__ __forceinline__ void mma_pass(uint32_t Bst, int cb,
                                         const uint32_t* a0, const uint32_t* a1,
                                         int n0w, int lane, float acc[2][8][4]) {
#pragma unroll
    for (int g = 0; g < 4; ++g) {
        const int row = n0w + g * 16 + (lane & 15);
        uint32_t bq[4];
        ldmx4(bq, Bst + row * 64 + (((cb + (lane >> 4)) ^ ((row >> 1) & 3)) << 4));
        mma_bf16(acc[0][2 * g],     a0, bq[0], bq[2]);
        mma_bf16(acc[0][2 * g + 1], a0, bq[1], bq[3]);
        mma_bf16(acc[1][2 * g],     a1, bq[0], bq[2]);
        mma_bf16(acc[1][2 * g + 1], a1, bq[1], bq[3]);
    }
}

__device__ __forceinline__ void split2(float v, __nv_bfloat16& h, __nv_bfloat16& l) {
    h = __float2bfloat16_rn(v);
    l = __float2bfloat16_rn(v - __bfloat162float(h));
}

// ---------------------------------------------------------------------------
// Prep kernels: pre-split to bf16 hi/lo
// ---------------------------------------------------------------------------
__global__ void prep_x_kernel(const float* __restrict__ x)
{
    const size_t idx = (size_t)blockIdx.x * 512 + threadIdx.x;
    if (idx >= (size_t)3 * BB * CIN * HIN * WPAD) return;
    const int w = idx & 127;
    size_t r = idx >> 7;
    const int h = r % HIN;  r /= HIN;
    const int c = r & 63;   r >>= 6;
    const int b = r & 7;
    const int kw = (int)(r >> 3);
    float v = 0.f;
    if (w + kw < WIN)
        v = x[(((size_t)b * CIN + c) * HIN + h) * WIN + w + kw];
    __nv_bfloat16 hi, lo; split2(v, hi, lo);
    g_xh[idx] = hi; g_xl[idx] = lo;
}

__global__ void prep_w_kernel(const float* __restrict__ ew,
                              const float* __restrict__ dw,
                              const float* __restrict__ rw)
{
    const int idx = blockIdx.x * 512 + threadIdx.x;
    if (idx < FS * KCONV) {
        __nv_bfloat16 hi, lo; split2(ew[idx], hi, lo);
        g_ewh[idx] = hi; g_ewl[idx] = lo;
    }
    const int j = idx - FS * KCONV;
    if (j >= 0 && j < NV * FS) {
        const int n = j >> 9, k = j & 511;
        float v = 0.f;
        if (n < DEC)            v = dw[n * FS + k];
        else if (n < DEC + RED) v = rw[(n - DEC) * FS + k];
        __nv_bfloat16 hi, lo; split2(v, hi, lo);
        g_w2h[j] = hi; g_w2l[j] = lo;
    }
}

// ---------------------------------------------------------------------------
// Kernel 1: conv3x3 + bias + relu -> g_hh/g_hl.  M=ow(128), N=filters(256)
// Two chunks per sync region, 6-deep cp.async ring.
// ---------------------------------------------------------------------------
__global__ void __launch_bounds__(512, 1)
conv_mma_kernel(const float* __restrict__ eb)
{
    extern __shared__ uint8_t smem[];
    const uint32_t sb = smem_u32(smem);
    const int tid = threadIdx.x, lane = tid & 31, wid = tid >> 5;
    const int m0w = (wid >> 2) * 32, n0w = (wid & 3) * 64;
    const int ftile = blockIdx.x, boh = blockIdx.y;
    const int b = boh / HO, oh = boh % HO;
    const int fbase = ftile * TN;

    // per-thread invariant staging roles
    const int ar = tid >> 4, acq = tid & 15;
    const int ahalf = ar >> 4, akr = ar & 15;

    auto issue_stage = [&](int ch) {            // ch < K1_NCH guaranteed by caller
        const uint32_t st = sb + (ch % NSTAGE) * STAGE_BYTES;
        const int k0 = ch * KC;
        {   // A: 32 rows (hi 0-15, lo 16-31) x 16 chunks = 512 ops
            const int k = k0 + akr;
            const int c = k / 9, t = k - c * 9, kh = t / 3, kw = t - kh * 3;
            const __nv_bfloat16* src = (ahalf ? g_xl : g_xh)
                + (((((size_t)kw * BB + b) * CIN + c) * HIN + oh + kh) << 7)
                + (acq << 3);
            cpa16(st + ahalf * 4096 + akr * 256 + ((acq ^ (akr & 7)) << 4), src);
        }
#pragma unroll
        for (int s = 0; s < 2; ++s) {   // B: 256 rows x 4 chunks = 1024 ops
            const int idx = tid + (s << 9);
            const int n = idx >> 2, cq = idx & 3;
            const __nv_bfloat16* src = (cq < 2 ? g_ewh : g_ewl)
                + (size_t)(fbase + n) * KCONV + k0 + ((cq & 1) << 3);
            cpa16(st + SM_B + n * 64 + ((cq ^ ((n >> 1) & 3)) << 4), src);
        }
    };
    auto maybe_issue = [&](int ch) {
        if (ch < K1_NCH) issue_stage(ch);
        CP_COMMIT();                     // empty group at tail keeps wait-count exact
    };

    float acc[2][8][4];
#pragma unroll
    for (int i = 0; i < 2; ++i)
#pragma unroll
        for (int j = 0; j < 8; ++j)
#pragma unroll
            for (int q = 0; q < 4; ++q) acc[i][j][q] = 0.f;

    maybe_issue(0); maybe_issue(1); maybe_issue(2); maybe_issue(3);

    for (int cc = 0; cc < K1_NCH; cc += 2) {
        CP_WAIT2();                      // stages cc, cc+1 complete
        __syncthreads();
        maybe_issue(cc + 4); maybe_issue(cc + 5);

#pragma unroll
        for (int d = 0; d < 2; ++d) {
            const uint32_t st = sb + ((cc + d) % NSTAGE) * STAGE_BYTES;
            uint32_t a0[4], a1[4];
            lda_t(a0, st, m0w, lane);
            lda_t(a1, st, m0w + 16, lane);
            mma_pass(st + SM_B, 0, a0, a1, n0w, lane, acc);   // Ah*Bh
            mma_pass(st + SM_B, 2, a0, a1, n0w, lane, acc);   // Ah*Bl
            lda_t(a0, st + 4096, m0w, lane);
            lda_t(a1, st + 4096, m0w + 16, lane);
            mma_pass(st + SM_B, 0, a0, a1, n0w, lane, acc);   // Al*Bh
        }
    }

    // epilogue: bias + relu, split hi/lo, write g_hh/g_hl [P][f]
    float ebv[16];
#pragma unroll
    for (int nj = 0; nj < 8; ++nj) {
        const int f = fbase + n0w + nj * 8 + (lane & 3) * 2;
        ebv[2 * nj]     = __ldg(&eb[f]);
        ebv[2 * nj + 1] = __ldg(&eb[f + 1]);
    }
#pragma unroll
    for (int mi = 0; mi < 2; ++mi) {
#pragma unroll
        for (int half = 0; half < 2; ++half) {
            const int ow = m0w + mi * 16 + half * 8 + (lane >> 2);
            if (ow < WO) {
                const size_t base = (size_t)((b * HO + oh) * WO + ow) * FS;
#pragma unroll
                for (int nj = 0; nj < 8; ++nj) {
                    const int f = fbase + n0w + nj * 8 + (lane & 3) * 2;
                    const float v0 = fmaxf(acc[mi][nj][half * 2 + 0] + ebv[2 * nj], 0.f);
                    const float v1 = fmaxf(acc[mi][nj][half * 2 + 1] + ebv[2 * nj + 1], 0.f);
                    __nv_bfloat16 h0, l0, h1, l1;
                    split2(v0, h0, l0); split2(v1, h1, l1);
                    const uint32_t ph = (uint32_t)__bfloat16_as_ushort(h0) |
                                        ((uint32_t)__bfloat16_as_ushort(h1) << 16);
                    const uint32_t pl = (uint32_t)__bfloat16_as_ushort(l0) |
                                        ((uint32_t)__bfloat16_as_ushort(l1) << 16);
                    *(uint32_t*)&g_hh[base + f] = ph;
                    *(uint32_t*)&g_hl[base + f] = pl;
                }
            }
        }
    }
}

// ---------------------------------------------------------------------------
// Kernel 2: fused dec/red 1x1 GEMM.  M=128 positions, N=256 virtual cols.
// NPASS=1: pure-dec tiles (bf16 hi only). NPASS=3: mixed dec/red tile.
// Two chunks per sync region, 6-deep cp.async ring.
// ---------------------------------------------------------------------------
template <int NPASS>
__global__ void __launch_bounds__(512, 1)
fc_mma_kernel(const float* __restrict__ x,
              const float* __restrict__ db, const float* __restrict__ rb,
              float* __restrict__ out, int ntbase)
{
    extern __shared__ uint8_t smem[];
    const uint32_t sb = smem_u32(smem);
    const int tid = threadIdx.x, lane = tid & 31, wid = tid >> 5;
    const int m0w = (wid >> 2) * 32, n0w = (wid & 3) * 64;
    const int nt = ntbase + blockIdx.x, mt = blockIdx.y;
    const int P0 = mt * TM, N0 = nt * TN;

    auto issue_stage = [&](int ch) {
        const uint32_t st = sb + (ch % NSTAGE) * STAGE_BYTES;
        const int k0 = ch * KC;
        const int nA   = (NPASS == 1) ? 256 : 512;
        const int nops = (NPASS == 1) ? 768 : 1536;
        for (int i = tid; i < nops; i += 512) {
            if (i < nA) {
                int m, cq; const __nv_bfloat16* g;
                if (NPASS == 1) { m = i >> 1; cq = i & 1; g = g_hh; }
                else            { m = i >> 2; cq = i & 3; g = (cq < 2) ? g_hh : g_hl; }
                const __nv_bfloat16* src = g + (size_t)(P0 + m) * FS + k0 + ((cq & 1) << 3);
                cpa16(st + m * 64 + ((cq ^ ((m >> 1) & 3)) << 4), src);
            } else {
                const int j = i - nA;
                int n, cq; const __nv_bfloat16* g;
                if (NPASS == 1) { n = j >> 1; cq = j & 1; g = g_w2h; }
                else            { n = j >> 2; cq = j & 3; g = (cq < 2) ? g_w2h : g_w2l; }
                const __nv_bfloat16* src = g + (size_t)(N0 + n) * FS + k0 + ((cq & 1) << 3);
                cpa16(st + SM_B + n * 64 + ((cq ^ ((n >> 1) & 3)) << 4), src);
            }
        }
    };
    auto maybe_issue = [&](int ch) {
        if (ch < K2_NCH) issue_stage(ch);
        CP_COMMIT();
    };

    float acc[2][8][4];
#pragma unroll
    for (int i = 0; i < 2; ++i)
#pragma unroll
        for (int j = 0; j < 8; ++j)
#pragma unroll
            for (int q = 0; q < 4; ++q) acc[i][j][q] = 0.f;

    maybe_issue(0); maybe_issue(1); maybe_issue(2); maybe_issue(3);

    for (int cc = 0; cc < K2_NCH; cc += 2) {
        CP_WAIT2();
        __syncthreads();
        maybe_issue(cc + 4); maybe_issue(cc + 5);

#pragma unroll
        for (int d = 0; d < 2; ++d) {
            const uint32_t st = sb + ((cc + d) % NSTAGE) * STAGE_BYTES;
            uint32_t a0[4], a1[4];
            lda_n(a0, st, 0, m0w, lane);
            lda_n(a1, st, 0, m0w + 16, lane);
            mma_pass(st + SM_B, 0, a0, a1, n0w, lane, acc);       // Ah*Bh
            if (NPASS == 3) {
                mma_pass(st + SM_B, 2, a0, a1, n0w, lane, acc);   // Ah*Bl
                lda_n(a0, st, 2, m0w, lane);
                lda_n(a1, st, 2, m0w + 16, lane);
                mma_pass(st + SM_B, 0, a0, a1, n0w, lane, acc);   // Al*Bh
            }
        }
    }

    // ---- epilogue: dec -> sigmoid/MSE partial, red -> output ----
    float lsum = 0.f;
#pragma unroll
    for (int mi = 0; mi < 2; ++mi) {
#pragma unroll
        for (int half = 0; half < 2; ++half) {
            const int m = m0w + mi * 16 + half * 8 + (lane >> 2);
            const int P = P0 + m;
            if (P < NPOS) {
                const int bb = P / (HO * WO);
                const int r2 = P - bb * (HO * WO);
                const int ohh = r2 / WO;
                const int oww = r2 - ohh * WO;
#pragma unroll
                for (int nj = 0; nj < 8; ++nj) {
#pragma unroll
                    for (int e = 0; e < 2; ++e) {
                        const int ng = N0 + n0w + nj * 8 + (lane & 3) * 2 + e;
                        const float val = acc[mi][nj][half * 2 + e];
                        if (ng < DEC) {
                            const int c = ng / 9, t = ng - c * 9;
                            const int kh = t / 3, kw = t - kh * 3;
                            const float z = val + __ldg(&db[ng]);
                            const float aux = 1.f / (1.f + expf(-z));
                            const float tg = x[(((size_t)bb * CIN + c) * HIN
                                               + ohh + kh) * WIN + oww + kw];
                            const float df = tg - aux;
                            lsum += df * df;
                        } else if (ng < DEC + RED) {
                            const int o = ng - DEC;
                            out[((size_t)bb * RED + o) * (HO * WO) + r2] =
                                val + __ldg(&rb[o]);
                        }
                    }
                }
            }
        }
    }

    __syncthreads();
    float* red_s = (float*)smem;
    red_s[tid] = lsum;
    __syncthreads();
#pragma unroll
    for (int s = 256; s > 0; s >>= 1) {
        if (tid < s) red_s[tid] += red_s[tid + s];
        __syncthreads();
    }
    if (tid == 0) g_part[mt * K2_NT + nt] = red_s[0];
}

// ---------------------------------------------------------------------------
// Kernel 3: final loss scalar (deterministic double accumulation)
// ---------------------------------------------------------------------------
__global__ void loss_reduce_kernel(float* __restrict__ out, int scalar_idx)
{
    __shared__ double s[256];
    double v = 0.0;
    for (int i = threadIdx.x; i < K2_MT * K2_NT; i += 256)
        v += (double)g_part[i];
    s[threadIdx.x] = v;
    __syncthreads();
#pragma unroll
    for (int st = 128; st > 0; st >>= 1) {
        if (threadIdx.x < st) s[threadIdx.x] += s[threadIdx.x + st];
        __syncthreads();
    }
    if (threadIdx.x == 0)
        out[scalar_idx] = (float)(s[0] / (double)((size_t)NPOS * DEC));
}

// ---------------------------------------------------------------------------
// Launch
// ---------------------------------------------------------------------------
extern "C" void kernel_launch(void* const* d_in, const int* in_sizes, int n_in,
                              void* d_out, int out_size)
{
    const float* x  = (const float*)d_in[0];
    const float* ew = (const float*)d_in[1];
    const float* eb = (const float*)d_in[2];
    const float* dw = (const float*)d_in[3];
    const float* db = (const float*)d_in[4];
    const float* rw = (const float*)d_in[5];
    const float* rb = (const float*)d_in[6];
    float* out = (float*)d_out;

    static bool attr_set = false;
    if (!attr_set) {
        cudaFuncSetAttribute(conv_mma_kernel,
                             cudaFuncAttributeMaxDynamicSharedMemorySize, SMEM_TOTAL);
        cudaFuncSetAttribute(fc_mma_kernel<1>,
                             cudaFuncAttributeMaxDynamicSharedMemorySize, SMEM_TOTAL);
        cudaFuncSetAttribute(fc_mma_kernel<3>,
                             cudaFuncAttributeMaxDynamicSharedMemorySize, SMEM_TOTAL);
        attr_set = true;
    }

    {   // pre-split inputs to bf16 hi/lo
        const size_t nx = (size_t)3 * BB * CIN * HIN * WPAD;
        prep_x_kernel<<<(unsigned)((nx + 511) / 512), 512>>>(x);
        const int nw = FS * KCONV + NV * FS;
        prep_w_kernel<<<(nw + 511) / 512, 512>>>(ew, dw, rw);
    }
    {   // conv3x3 -> H (bf16 hi/lo)
        dim3 grid(FS / TN, BB * HO);                 // (2, 880)
        conv_mma_kernel<<<grid, 512, SMEM_TOTAL>>>(eb);
    }
    {   // fc: pure-dec tiles (1-pass) and mixed dec/red tile (3-pass)
        dim3 grid_a(2, K2_MT);
        fc_mma_kernel<1><<<grid_a, 512, SMEM_TOTAL>>>(x, db, rb, out, 0);
        dim3 grid_b(1, K2_MT);
        fc_mma_kernel<3><<<grid_b, 512, SMEM_TOTAL>>>(x, db, rb, out, 2);
    }
    loss_reduce_kernel<<<1, 256>>>(out, out_size - 1);
}

// round 7
// speedup vs baseline: 3.0985x; 1.1291x over previous
#include <cuda_runtime.h>
#include <cuda_bf16.h>
#include <cstdint>
#include <math.h>

// ---------------------------------------------------------------------------
// Problem constants
// ---------------------------------------------------------------------------
#define BB    8
#define CIN   64
#define FS    512
#define HIN   112
#define WIN   112
#define WPAD  128
#define HO    110
#define WO    110
#define NPOS  (BB * HO * WO)            // 96800
#define NPOSP (757 * 128)               // 96896 padded
#define DEC   576
#define RED   128
#define KCONV 576
#define NV    768                       // virtual N for fc (dec+red+pad)

#define TM 128
#define TN 128
#define KC 16

#define K1_NCH (KCONV / KC)             // 36
#define K2_NCH (FS / KC)                // 32
#define K2_MT  757
#define K2_NT  6

#define NSTAGE 6
// conv / fc3 stage: A 8KB + B 8KB.  fc1 stage: A 4KB + B 4KB.
#define STG_BIG   16384
#define SMB_BIG   8192
#define STG_SMALL 8192
#define SMB_SMALL 4096
#define SMEM_BIG   (NSTAGE * STG_BIG)     // 98304
#define SMEM_SMALL (NSTAGE * STG_SMALL)   // 49152

// ---------------------------------------------------------------------------
// Device scratch (bf16 hi/lo pre-split)
// ---------------------------------------------------------------------------
__device__ __nv_bfloat16 g_xh[(size_t)3 * BB * CIN * HIN * WPAD];   // 44 MB
__device__ __nv_bfloat16 g_xl[(size_t)3 * BB * CIN * HIN * WPAD];
__device__ __nv_bfloat16 g_ewh[FS * KCONV];
__device__ __nv_bfloat16 g_ewl[FS * KCONV];
__device__ __nv_bfloat16 g_w2h[NV * FS];
__device__ __nv_bfloat16 g_w2l[NV * FS];
__device__ __nv_bfloat16 g_hh[(size_t)NPOSP * FS];                  // 99 MB
__device__ __nv_bfloat16 g_hl[(size_t)NPOSP * FS];
__device__ float g_part[K2_MT * K2_NT];

// ---------------------------------------------------------------------------
// helpers
// ---------------------------------------------------------------------------
__device__ __forceinline__ uint32_t smem_u32(const void* p) {
    uint32_t a;
    asm("{ .reg .u64 t; cvta.to.shared.u64 t, %1; cvt.u32.u64 %0, t; }"
        : "=r"(a) : "l"(p));
    return a;
}
__device__ __forceinline__ void cpa16(uint32_t dst, const void* src) {
    asm volatile("cp.async.cg.shared.global [%0], [%1], 16;"
                 :: "r"(dst), "l"(src));
}
#define CP_COMMIT() asm volatile("cp.async.commit_group;" ::: "memory")
#define CP_WAIT2()  asm volatile("cp.async.wait_group 2;" ::: "memory")

__device__ __forceinline__ void ldmx4(uint32_t* r, uint32_t addr) {
    asm volatile("ldmatrix.sync.aligned.m8n8.x4.shared.b16 {%0,%1,%2,%3}, [%4];"
                 : "=r"(r[0]), "=r"(r[1]), "=r"(r[2]), "=r"(r[3]) : "r"(addr));
}
__device__ __forceinline__ void ldmx4t(uint32_t* r, uint32_t addr) {
    asm volatile("ldmatrix.sync.aligned.m8n8.x4.trans.shared.b16 {%0,%1,%2,%3}, [%4];"
                 : "=r"(r[0]), "=r"(r[1]), "=r"(r[2]), "=r"(r[3]) : "r"(addr));
}
__device__ __forceinline__ void mma_bf16(float* c, const uint32_t* a,
                                         uint32_t b0, uint32_t b1) {
    asm volatile("mma.sync.aligned.m16n8k16.row.col.f32.bf16.bf16.f32 "
                 "{%0,%1,%2,%3}, {%4,%5,%6,%7}, {%8,%9}, {%0,%1,%2,%3};"
                 : "+f"(c[0]), "+f"(c[1]), "+f"(c[2]), "+f"(c[3])
                 : "r"(a[0]), "r"(a[1]), "r"(a[2]), "r"(a[3]), "r"(b0), "r"(b1));
}

// A fragment from [k16][m128] tile (256B pitch, chunk^(k&7) swizzle), transposed
__device__ __forceinline__ void lda_t(uint32_t* a, uint32_t base, int m0, int lane) {
    const int kk  = (lane & 7) | ((lane >> 4) << 3);
    const int mch = (m0 >> 3) + ((lane >> 3) & 1);
    ldmx4t(a, base + kk * 256 + ((mch ^ (kk & 7)) << 4));
}
// A fragment from [m128][64B] tile, non-transposed. ca: 0=hi, 2=lo
__device__ __forceinline__ void lda64(uint32_t* a, uint32_t base, int ca,
                                      int m0, int lane) {
    const int row = m0 + (lane & 15);
    ldmx4(a, base + row * 64 + (((ca + (lane >> 4)) ^ ((row >> 1) & 3)) << 4));
}
// A fragment from [m128][32B] tile (hi only, no swizzle needed)
__device__ __forceinline__ void lda32(uint32_t* a, uint32_t base, int m0, int lane) {
    const int row = m0 + (lane & 15);
    ldmx4(a, base + row * 32 + ((lane >> 4) << 4));
}

// One pass over 64 n-columns, B in 64B-pitch swizzled tile. cb: 0=hi, 2=lo.
__device__ __forceinline__ void mma_pass64(uint32_t Bst, int cb,
                                           const uint32_t* a0, const uint32_t* a1,
                                           int n0w, int lane, float acc[2][8][4]) {
#pragma unroll
    for (int g = 0; g < 4; ++g) {
        const int row = n0w + g * 16 + (lane & 15);
        uint32_t bq[4];
        ldmx4(bq, Bst + row * 64 + (((cb + (lane >> 4)) ^ ((row >> 1) & 3)) << 4));
        mma_bf16(acc[0][2 * g],     a0, bq[0], bq[2]);
        mma_bf16(acc[0][2 * g + 1], a0, bq[1], bq[3]);
        mma_bf16(acc[1][2 * g],     a1, bq[0], bq[2]);
        mma_bf16(acc[1][2 * g + 1], a1, bq[1], bq[3]);
    }
}
// One pass over 64 n-columns, B in 32B-pitch tile (hi only).
__device__ __forceinline__ void mma_pass32(uint32_t Bst,
                                           const uint32_t* a0, const uint32_t* a1,
                                           int n0w, int lane, float acc[2][8][4]) {
#pragma unroll
    for (int g = 0; g < 4; ++g) {
        const int row = n0w + g * 16 + (lane & 15);
        uint32_t bq[4];
        ldmx4(bq, Bst + row * 32 + ((lane >> 4) << 4));
        mma_bf16(acc[0][2 * g],     a0, bq[0], bq[2]);
        mma_bf16(acc[0][2 * g + 1], a0, bq[1], bq[3]);
        mma_bf16(acc[1][2 * g],     a1, bq[0], bq[2]);
        mma_bf16(acc[1][2 * g + 1], a1, bq[1], bq[3]);
    }
}

__device__ __forceinline__ void split2(float v, __nv_bfloat16& h, __nv_bfloat16& l) {
    h = __float2bfloat16_rn(v);
    l = __float2bfloat16_rn(v - __bfloat162float(h));
}

// ---------------------------------------------------------------------------
// Prep kernels: pre-split to bf16 hi/lo
// ---------------------------------------------------------------------------
__global__ void prep_x_kernel(const float* __restrict__ x)
{
    const size_t idx = (size_t)blockIdx.x * 512 + threadIdx.x;
    if (idx >= (size_t)3 * BB * CIN * HIN * WPAD) return;
    const int w = idx & 127;
    size_t r = idx >> 7;
    const int h = r % HIN;  r /= HIN;
    const int c = r & 63;   r >>= 6;
    const int b = r & 7;
    const int kw = (int)(r >> 3);
    float v = 0.f;
    if (w + kw < WIN)
        v = x[(((size_t)b * CIN + c) * HIN + h) * WIN + w + kw];
    __nv_bfloat16 hi, lo; split2(v, hi, lo);
    g_xh[idx] = hi; g_xl[idx] = lo;
}

__global__ void prep_w_kernel(const float* __restrict__ ew,
                              const float* __restrict__ dw,
                              const float* __restrict__ rw)
{
    const int idx = blockIdx.x * 512 + threadIdx.x;
    if (idx < FS * KCONV) {
        __nv_bfloat16 hi, lo; split2(ew[idx], hi, lo);
        g_ewh[idx] = hi; g_ewl[idx] = lo;
    }
    const int j = idx - FS * KCONV;
    if (j >= 0 && j < NV * FS) {
        const int n = j >> 9, k = j & 511;
        float v = 0.f;
        if (n < DEC)            v = dw[n * FS + k];
        else if (n < DEC + RED) v = rw[(n - DEC) * FS + k];
        __nv_bfloat16 hi, lo; split2(v, hi, lo);
        g_w2h[j] = hi; g_w2l[j] = lo;
    }
}

// ---------------------------------------------------------------------------
// Kernel 1: conv3x3 + bias + relu -> g_hh/g_hl.  M=ow(128), N=filters(128)
// 256 threads / 8 warps, 2 CTAs per SM. 6-deep cp.async ring.
// ---------------------------------------------------------------------------
__global__ void __launch_bounds__(256, 2)
conv_mma_kernel(const float* __restrict__ eb)
{
    extern __shared__ uint8_t smem[];
    const uint32_t sb = smem_u32(smem);
    const int tid = threadIdx.x, lane = tid & 31, wid = tid >> 5;
    const int m0w = (wid >> 1) * 32, n0w = (wid & 1) * 64;
    const int ftile = blockIdx.x, boh = blockIdx.y;
    const int b = boh / HO, oh = boh % HO;
    const int fbase = ftile * TN;

    auto issue_stage = [&](int ch) {
        const uint32_t st = sb + (ch % NSTAGE) * STG_BIG;
        const int k0 = ch * KC;
#pragma unroll
        for (int s = 0; s < 2; ++s) {   // A: 32 k-rows (hi/lo) x 16 m-chunks
            const int idx = tid + (s << 8);
            const int ar = idx >> 4, acq = idx & 15;
            const int ahalf = ar >> 4, akr = ar & 15;
            const int k = k0 + akr;
            const int c = k / 9, t = k - c * 9, kh = t / 3, kw = t - kh * 3;
            const __nv_bfloat16* src = (ahalf ? g_xl : g_xh)
                + (((((size_t)kw * BB + b) * CIN + c) * HIN + oh + kh) << 7)
                + (acq << 3);
            cpa16(st + ahalf * 4096 + akr * 256 + ((acq ^ (akr & 7)) << 4), src);
        }
#pragma unroll
        for (int s = 0; s < 2; ++s) {   // B: 128 rows x 4 chunks
            const int idx = tid + (s << 8);
            const int n = idx >> 2, cq = idx & 3;
            const __nv_bfloat16* src = (cq < 2 ? g_ewh : g_ewl)
                + (size_t)(fbase + n) * KCONV + k0 + ((cq & 1) << 3);
            cpa16(st + SMB_BIG + n * 64 + ((cq ^ ((n >> 1) & 3)) << 4), src);
        }
    };
    auto maybe_issue = [&](int ch) {
        if (ch < K1_NCH) issue_stage(ch);
        CP_COMMIT();
    };

    float acc[2][8][4];
#pragma unroll
    for (int i = 0; i < 2; ++i)
#pragma unroll
        for (int j = 0; j < 8; ++j)
#pragma unroll
            for (int q = 0; q < 4; ++q) acc[i][j][q] = 0.f;

    maybe_issue(0); maybe_issue(1); maybe_issue(2); maybe_issue(3);

    for (int cc = 0; cc < K1_NCH; cc += 2) {
        CP_WAIT2();
        __syncthreads();
        maybe_issue(cc + 4); maybe_issue(cc + 5);

#pragma unroll
        for (int d = 0; d < 2; ++d) {
            const uint32_t st = sb + ((cc + d) % NSTAGE) * STG_BIG;
            uint32_t a0[4], a1[4];
            lda_t(a0, st, m0w, lane);
            lda_t(a1, st, m0w + 16, lane);
            mma_pass64(st + SMB_BIG, 0, a0, a1, n0w, lane, acc);   // Ah*Bh
            mma_pass64(st + SMB_BIG, 2, a0, a1, n0w, lane, acc);   // Ah*Bl
            lda_t(a0, st + 4096, m0w, lane);
            lda_t(a1, st + 4096, m0w + 16, lane);
            mma_pass64(st + SMB_BIG, 0, a0, a1, n0w, lane, acc);   // Al*Bh
        }
    }

    // epilogue: bias + relu, split hi/lo, write g_hh/g_hl [P][f]
    float ebv[16];
#pragma unroll
    for (int nj = 0; nj < 8; ++nj) {
        const int f = fbase + n0w + nj * 8 + (lane & 3) * 2;
        ebv[2 * nj]     = __ldg(&eb[f]);
        ebv[2 * nj + 1] = __ldg(&eb[f + 1]);
    }
#pragma unroll
    for (int mi = 0; mi < 2; ++mi) {
#pragma unroll
        for (int half = 0; half < 2; ++half) {
            const int ow = m0w + mi * 16 + half * 8 + (lane >> 2);
            if (ow < WO) {
                const size_t base = (size_t)((b * HO + oh) * WO + ow) * FS;
#pragma unroll
                for (int nj = 0; nj < 8; ++nj) {
                    const int f = fbase + n0w + nj * 8 + (lane & 3) * 2;
                    const float v0 = fmaxf(acc[mi][nj][half * 2 + 0] + ebv[2 * nj], 0.f);
                    const float v1 = fmaxf(acc[mi][nj][half * 2 + 1] + ebv[2 * nj + 1], 0.f);
                    __nv_bfloat16 h0, l0, h1, l1;
                    split2(v0, h0, l0); split2(v1, h1, l1);
                    const uint32_t ph = (uint32_t)__bfloat16_as_ushort(h0) |
                                        ((uint32_t)__bfloat16_as_ushort(h1) << 16);
                    const uint32_t pl = (uint32_t)__bfloat16_as_ushort(l0) |
                                        ((uint32_t)__bfloat16_as_ushort(l1) << 16);
                    *(uint32_t*)&g_hh[base + f] = ph;
                    *(uint32_t*)&g_hl[base + f] = pl;
                }
            }
        }
    }
}

// ---------------------------------------------------------------------------
// Kernel 2: fused dec/red 1x1 GEMM.  M=128 positions, N=128 virtual cols.
// Virtual cols: [0,576) dec, [576,704) red, [704,768) pad.
// NPASS=1: pure-dec tiles (nt 0..3). NPASS=3: mixed tiles (nt 4,5).
// 256 threads / 8 warps, 2 CTAs per SM.
// ---------------------------------------------------------------------------
template <int NPASS>
__global__ void __launch_bounds__(256, 2)
fc_mma_kernel(const float* __restrict__ x,
              const float* __restrict__ db, const float* __restrict__ rb,
              float* __restrict__ out, int ntbase)
{
    extern __shared__ uint8_t smem[];
    const uint32_t sb = smem_u32(smem);
    const int tid = threadIdx.x, lane = tid & 31, wid = tid >> 5;
    const int m0w = (wid >> 1) * 32, n0w = (wid & 1) * 64;
    const int nt = ntbase + blockIdx.x, mt = blockIdx.y;
    const int P0 = mt * TM, N0 = nt * TN;

    constexpr int STG = (NPASS == 1) ? STG_SMALL : STG_BIG;
    constexpr int SMB = (NPASS == 1) ? SMB_SMALL : SMB_BIG;

    auto issue_stage = [&](int ch) {
        const uint32_t st = sb + (ch % NSTAGE) * STG;
        const int k0 = ch * KC;
        if (NPASS == 1) {
#pragma unroll
            for (int s = 0; s < 2; ++s) {      // 512 ops: 256 A + 256 B, hi only
                const int idx = tid + (s << 8);
                if (idx < 256) {
                    const int m = idx >> 1, cq = idx & 1;
                    const __nv_bfloat16* src = g_hh + (size_t)(P0 + m) * FS + k0 + (cq << 3);
                    cpa16(st + m * 32 + (cq << 4), src);
                } else {
                    const int j = idx - 256;
                    const int n = j >> 1, cq = j & 1;
                    const __nv_bfloat16* src = g_w2h + (size_t)(N0 + n) * FS + k0 + (cq << 3);
                    cpa16(st + SMB + n * 32 + (cq << 4), src);
                }
            }
        } else {
#pragma unroll
            for (int s = 0; s < 4; ++s) {      // 1024 ops: 512 A + 512 B, hi+lo
                const int idx = tid + (s << 8);
                if (idx < 512) {
                    const int m = idx >> 2, cq = idx & 3;
                    const __nv_bfloat16* g = (cq < 2) ? g_hh : g_hl;
                    const __nv_bfloat16* src = g + (size_t)(P0 + m) * FS + k0 + ((cq & 1) << 3);
                    cpa16(st + m * 64 + ((cq ^ ((m >> 1) & 3)) << 4), src);
                } else {
                    const int j = idx - 512;
                    const int n = j >> 2, cq = j & 3;
                    const __nv_bfloat16* g = (cq < 2) ? g_w2h : g_w2l;
                    const __nv_bfloat16* src = g + (size_t)(N0 + n) * FS + k0 + ((cq & 1) << 3);
                    cpa16(st + SMB + n * 64 + ((cq ^ ((n >> 1) & 3)) << 4), src);
                }
            }
        }
    };
    auto maybe_issue = [&](int ch) {
        if (ch < K2_NCH) issue_stage(ch);
        CP_COMMIT();
    };

    float acc[2][8][4];
#pragma unroll
    for (int i = 0; i < 2; ++i)
#pragma unroll
        for (int j = 0; j < 8; ++j)
#pragma unroll
            for (int q = 0; q < 4; ++q) acc[i][j][q] = 0.f;

    maybe_issue(0); maybe_issue(1); maybe_issue(2); maybe_issue(3);

    for (int cc = 0; cc < K2_NCH; cc += 2) {
        CP_WAIT2();
        __syncthreads();
        maybe_issue(cc + 4); maybe_issue(cc + 5);

#pragma unroll
        for (int d = 0; d < 2; ++d) {
            const uint32_t st = sb + ((cc + d) % NSTAGE) * STG;
            uint32_t a0[4], a1[4];
            if (NPASS == 1) {
                lda32(a0, st, m0w, lane);
                lda32(a1, st, m0w + 16, lane);
                mma_pass32(st + SMB, a0, a1, n0w, lane, acc);
            } else {
                lda64(a0, st, 0, m0w, lane);
                lda64(a1, st, 0, m0w + 16, lane);
                mma_pass64(st + SMB, 0, a0, a1, n0w, lane, acc);     // Ah*Bh
                mma_pass64(st + SMB, 2, a0, a1, n0w, lane, acc);     // Ah*Bl
                lda64(a0, st, 2, m0w, lane);
                lda64(a1, st, 2, m0w + 16, lane);
                mma_pass64(st + SMB, 0, a0, a1, n0w, lane, acc);     // Al*Bh
            }
        }
    }

    // ---- epilogue: dec -> sigmoid/MSE partial, red -> output ----
    float lsum = 0.f;
#pragma unroll
    for (int mi = 0; mi < 2; ++mi) {
#pragma unroll
        for (int half = 0; half < 2; ++half) {
            const int m = m0w + mi * 16 + half * 8 + (lane >> 2);
            const int P = P0 + m;
            if (P < NPOS) {
                const int bb = P / (HO * WO);
                const int r2 = P - bb * (HO * WO);
                const int ohh = r2 / WO;
                const int oww = r2 - ohh * WO;
#pragma unroll
                for (int nj = 0; nj < 8; ++nj) {
#pragma unroll
                    for (int e = 0; e < 2; ++e) {
                        const int ng = N0 + n0w + nj * 8 + (lane & 3) * 2 + e;
                        const float val = acc[mi][nj][half * 2 + e];
                        if (ng < DEC) {
                            const int c = ng / 9, t = ng - c * 9;
                            const int kh = t / 3, kw = t - kh * 3;
                            const float z = val + __ldg(&db[ng]);
                            const float aux = 1.f / (1.f + expf(-z));
                            const float tg = x[(((size_t)bb * CIN + c) * HIN
                                               + ohh + kh) * WIN + oww + kw];
                            const float df = tg - aux;
                            lsum += df * df;
                        } else if (ng < DEC + RED) {
                            const int o = ng - DEC;
                            out[((size_t)bb * RED + o) * (HO * WO) + r2] =
                                val + __ldg(&rb[o]);
                        }
                    }
                }
            }
        }
    }

    __syncthreads();
    float* red_s = (float*)smem;
    red_s[tid] = lsum;
    __syncthreads();
#pragma unroll
    for (int s = 128; s > 0; s >>= 1) {
        if (tid < s) red_s[tid] += red_s[tid + s];
        __syncthreads();
    }
    if (tid == 0) g_part[mt * K2_NT + nt] = red_s[0];
}

// ---------------------------------------------------------------------------
// Kernel 3: final loss scalar (deterministic double accumulation)
// ---------------------------------------------------------------------------
__global__ void loss_reduce_kernel(float* __restrict__ out, int scalar_idx)
{
    __shared__ double s[256];
    double v = 0.0;
    for (int i = threadIdx.x; i < K2_MT * K2_NT; i += 256)
        v += (double)g_part[i];
    s[threadIdx.x] = v;
    __syncthreads();
#pragma unroll
    for (int st = 128; st > 0; st >>= 1) {
        if (threadIdx.x < st) s[threadIdx.x] += s[threadIdx.x + st];
        __syncthreads();
    }
    if (threadIdx.x == 0)
        out[scalar_idx] = (float)(s[0] / (double)((size_t)NPOS * DEC));
}

// ---------------------------------------------------------------------------
// Launch
// ---------------------------------------------------------------------------
extern "C" void kernel_launch(void* const* d_in, const int* in_sizes, int n_in,
                              void* d_out, int out_size)
{
    const float* x  = (const float*)d_in[0];
    const float* ew = (const float*)d_in[1];
    const float* eb = (const float*)d_in[2];
    const float* dw = (const float*)d_in[3];
    const float* db = (const float*)d_in[4];
    const float* rw = (const float*)d_in[5];
    const float* rb = (const float*)d_in[6];
    float* out = (float*)d_out;

    static bool attr_set = false;
    if (!attr_set) {
        cudaFuncSetAttribute(conv_mma_kernel,
                             cudaFuncAttributeMaxDynamicSharedMemorySize, SMEM_BIG);
        cudaFuncSetAttribute(fc_mma_kernel<1>,
                             cudaFuncAttributeMaxDynamicSharedMemorySize, SMEM_SMALL);
        cudaFuncSetAttribute(fc_mma_kernel<3>,
                             cudaFuncAttributeMaxDynamicSharedMemorySize, SMEM_BIG);
        attr_set = true;
    }

    {   // pre-split inputs to bf16 hi/lo
        const size_t nx = (size_t)3 * BB * CIN * HIN * WPAD;
        prep_x_kernel<<<(unsigned)((nx + 511) / 512), 512>>>(x);
        const int nw = FS * KCONV + NV * FS;
        prep_w_kernel<<<(nw + 511) / 512, 512>>>(ew, dw, rw);
    }
    {   // conv3x3 -> H (bf16 hi/lo)
        dim3 grid(FS / TN, BB * HO);                 // (4, 880)
        conv_mma_kernel<<<grid, 256, SMEM_BIG>>>(eb);
    }
    {   // fc: 4 pure-dec 1-pass tiles + 2 mixed 3-pass tiles
        dim3 grid_a(4, K2_MT);
        fc_mma_kernel<1><<<grid_a, 256, SMEM_SMALL>>>(x, db, rb, out, 0);
        dim3 grid_b(2, K2_MT);
        fc_mma_kernel<3><<<grid_b, 256, SMEM_BIG>>>(x, db, rb, out, 4);
    }
    loss_reduce_kernel<<<1, 256>>>(out, out_size - 1);
}

// round 9
// speedup vs baseline: 3.2534x; 1.0500x over previous
#include <cuda_runtime.h>
#include <cuda_bf16.h>
#include <cstdint>
#include <math.h>

// ---------------------------------------------------------------------------
// Problem constants
// ---------------------------------------------------------------------------
#define BB    8
#define CIN   64
#define FS    512
#define HIN   112
#define WIN   112
#define WPAD  128
#define HO    110
#define WO    110
#define NPOS  (BB * HO * WO)            // 96800
#define NPOSP (1513 * 64)               // 96832 padded (64-row m-tiles)
#define DEC   576
#define RED   128
#define KCONV 576
#define NV    768                       // virtual N rows for fc weights

#define TM 64                           // CTA m-tile
#define TN 128                          // CTA n-tile
#define KC 16

#define K1_NCH (KCONV / KC)             // 36
#define K2_NCH (FS / KC)                // 32
#define K2_MT  1513
#define FC1_NT 5                        // dec cols 0..639 (last 64 discarded)
#define RED_N0 576                      // fc3 single tile: cols 576..703 = red

#define NSTAGE 6
#define STG_BIG   12288                 // A 4KB + B 8KB (conv, fc3)
#define SMB_BIG   4096
#define STG_SMALL 6144                  // A 2KB + B 4KB (fc1)
#define SMB_SMALL 2048
#define SMEM_BIG   (NSTAGE * STG_BIG)     // 73728
#define SMEM_SMALL (NSTAGE * STG_SMALL)   // 36864

#define LOSS_N (K2_MT * FC1_NT)         // 7565

// ---------------------------------------------------------------------------
// Device scratch (bf16 hi/lo pre-split)
// ---------------------------------------------------------------------------
__device__ __nv_bfloat16 g_xh[(size_t)3 * BB * CIN * HIN * WPAD];
__device__ __nv_bfloat16 g_xl[(size_t)3 * BB * CIN * HIN * WPAD];
__device__ __nv_bfloat16 g_ewh[FS * KCONV];
__device__ __nv_bfloat16 g_ewl[FS * KCONV];
__device__ __nv_bfloat16 g_w2h[NV * FS];
__device__ __nv_bfloat16 g_w2l[NV * FS];
__device__ __nv_bfloat16 g_hh[(size_t)NPOSP * FS];
__device__ __nv_bfloat16 g_hl[(size_t)NPOSP * FS];
__device__ float g_part[LOSS_N];

// ---------------------------------------------------------------------------
// helpers
// ---------------------------------------------------------------------------
__device__ __forceinline__ uint32_t smem_u32(const void* p) {
    uint32_t a;
    asm("{ .reg .u64 t; cvta.to.shared.u64 t, %1; cvt.u32.u64 %0, t; }"
        : "=r"(a) : "l"(p));
    return a;
}
__device__ __forceinline__ void cpa16(uint32_t dst, const void* src) {
    asm volatile("cp.async.cg.shared.global [%0], [%1], 16;"
                 :: "r"(dst), "l"(src));
}
#define CP_COMMIT() asm volatile("cp.async.commit_group;" ::: "memory")
#define CP_WAIT2()  asm volatile("cp.async.wait_group 2;" ::: "memory")

__device__ __forceinline__ void ldmx4(uint32_t* r, uint32_t addr) {
    asm volatile("ldmatrix.sync.aligned.m8n8.x4.shared.b16 {%0,%1,%2,%3}, [%4];"
                 : "=r"(r[0]), "=r"(r[1]), "=r"(r[2]), "=r"(r[3]) : "r"(addr));
}
__device__ __forceinline__ void ldmx4t(uint32_t* r, uint32_t addr) {
    asm volatile("ldmatrix.sync.aligned.m8n8.x4.trans.shared.b16 {%0,%1,%2,%3}, [%4];"
                 : "=r"(r[0]), "=r"(r[1]), "=r"(r[2]), "=r"(r[3]) : "r"(addr));
}
__device__ __forceinline__ void mma_bf16(float* c, const uint32_t* a,
                                         uint32_t b0, uint32_t b1) {
    asm volatile("mma.sync.aligned.m16n8k16.row.col.f32.bf16.bf16.f32 "
                 "{%0,%1,%2,%3}, {%4,%5,%6,%7}, {%8,%9}, {%0,%1,%2,%3};"
                 : "+f"(c[0]), "+f"(c[1]), "+f"(c[2]), "+f"(c[3])
                 : "r"(a[0]), "r"(a[1]), "r"(a[2]), "r"(a[3]), "r"(b0), "r"(b1));
}

// A fragment from conv [k32][m64] transposed tile (128B pitch, chunk^(k&7))
__device__ __forceinline__ void lda_t(uint32_t* a, uint32_t base, int m0, int lane) {
    const int kk  = (lane & 7) | ((lane >> 4) << 3);
    const int mch = (m0 >> 3) + ((lane >> 3) & 1);
    ldmx4t(a, base + kk * 128 + ((mch ^ (kk & 7)) << 4));
}
// A fragment from [m64][64B] hi/lo tile. ca: 0=hi, 2=lo
__device__ __forceinline__ void lda64(uint32_t* a, uint32_t base, int ca,
                                      int m0, int lane) {
    const int row = m0 + (lane & 15);
    ldmx4(a, base + row * 64 + (((ca + (lane >> 4)) ^ ((row >> 1) & 3)) << 4));
}
// A fragment from [m64][32B] hi-only tile, swizzle cq ^ ((row>>2)&1)
__device__ __forceinline__ void lda32(uint32_t* a, uint32_t base, int m0, int lane) {
    const int row = m0 + (lane & 15);
    ldmx4(a, base + row * 32 + (((lane >> 4) ^ ((row >> 2) & 1)) << 4));
}

// One pass over 32 n-columns, B in 64B-pitch swizzled tile. cb: 0=hi, 2=lo.
__device__ __forceinline__ void mma_pass64(uint32_t Bst, int cb,
                                           const uint32_t* a0, const uint32_t* a1,
                                           int n0w, int lane, float acc[2][4][4]) {
#pragma unroll
    for (int g = 0; g < 2; ++g) {
        const int row = n0w + g * 16 + (lane & 15);
        uint32_t bq[4];
        ldmx4(bq, Bst + row * 64 + (((cb + (lane >> 4)) ^ ((row >> 1) & 3)) << 4));
        mma_bf16(acc[0][2 * g],     a0, bq[0], bq[2]);
        mma_bf16(acc[0][2 * g + 1], a0, bq[1], bq[3]);
        mma_bf16(acc[1][2 * g],     a1, bq[0], bq[2]);
        mma_bf16(acc[1][2 * g + 1], a1, bq[1], bq[3]);
    }
}
// One pass over 32 n-columns, B in 32B-pitch hi-only tile.
__device__ __forceinline__ void mma_pass32(uint32_t Bst,
                                           const uint32_t* a0, const uint32_t* a1,
                                           int n0w, int lane, float acc[2][4][4]) {
#pragma unroll
    for (int g = 0; g < 2; ++g) {
        const int row = n0w + g * 16 + (lane & 15);
        uint32_t bq[4];
        ldmx4(bq, Bst + row * 32 + (((lane >> 4) ^ ((row >> 2) & 1)) << 4));
        mma_bf16(acc[0][2 * g],     a0, bq[0], bq[2]);
        mma_bf16(acc[0][2 * g + 1], a0, bq[1], bq[3]);
        mma_bf16(acc[1][2 * g],     a1, bq[0], bq[2]);
        mma_bf16(acc[1][2 * g + 1], a1, bq[1], bq[3]);
    }
}

__device__ __forceinline__ void split2(float v, __nv_bfloat16& h, __nv_bfloat16& l) {
    h = __float2bfloat16_rn(v);
    l = __float2bfloat16_rn(v - __bfloat162float(h));
}

// ---------------------------------------------------------------------------
// Prep kernels
// ---------------------------------------------------------------------------
__global__ void prep_x_kernel(const float* __restrict__ x)
{
    const size_t idx = (size_t)blockIdx.x * 512 + threadIdx.x;
    if (idx >= (size_t)3 * BB * CIN * HIN * WPAD) return;
    const int w = idx & 127;
    size_t r = idx >> 7;
    const int h = r % HIN;  r /= HIN;
    const int c = r & 63;   r >>= 6;
    const int b = r & 7;
    const int kw = (int)(r >> 3);
    float v = 0.f;
    if (w + kw < WIN)
        v = x[(((size_t)b * CIN + c) * HIN + h) * WIN + w + kw];
    __nv_bfloat16 hi, lo; split2(v, hi, lo);
    g_xh[idx] = hi; g_xl[idx] = lo;
}

__global__ void prep_w_kernel(const float* __restrict__ ew,
                              const float* __restrict__ dw,
                              const float* __restrict__ rw)
{
    const int idx = blockIdx.x * 512 + threadIdx.x;
    if (idx < FS * KCONV) {
        __nv_bfloat16 hi, lo; split2(ew[idx], hi, lo);
        g_ewh[idx] = hi; g_ewl[idx] = lo;
    }
    const int j = idx - FS * KCONV;
    if (j >= 0 && j < NV * FS) {
        const int n = j >> 9, k = j & 511;
        float v = 0.f;
        if (n < DEC)            v = dw[n * FS + k];
        else if (n < DEC + RED) v = rw[(n - DEC) * FS + k];
        __nv_bfloat16 hi, lo; split2(v, hi, lo);
        g_w2h[j] = hi; g_w2l[j] = lo;
    }
}

// ---------------------------------------------------------------------------
// Kernel 1: conv3x3 + bias + relu -> g_hh/g_hl.  CTA tile 64 ow x 128 f.
// 8 warps (2m x 4n), warp tile 32x32, 3 CTAs/SM target.
// ---------------------------------------------------------------------------
__global__ void __launch_bounds__(256, 3)
conv_mma_kernel(const float* __restrict__ eb)
{
    extern __shared__ uint8_t smem[];
    const uint32_t sb = smem_u32(smem);
    const int tid = threadIdx.x, lane = tid & 31, wid = tid >> 5;
    const int m0w = (wid >> 2) * 32, n0w = (wid & 3) * 32;
    const int bx = blockIdx.x, boh = blockIdx.y;
    const int ftile = bx >> 1, mhalf = bx & 1;
    const int b = boh / HO, oh = boh % HO;
    const int fbase = ftile * TN;
    const int owbase = mhalf * 64;

    auto issue_stage = [&](int ch) {
        const uint32_t st = sb + (ch % NSTAGE) * STG_BIG;
        const int k0 = ch * KC;
        {   // A: 2 halves x 16 k-rows x 8 m-chunks = 256 ops (1/thread)
            const int ahalf = tid >> 7;
            const int rem = tid & 127;
            const int akr = rem >> 3, acq = rem & 7;
            const int k = k0 + akr;
            const int c = k / 9, t = k - c * 9, kh = t / 3, kw = t - kh * 3;
            const __nv_bfloat16* src = (ahalf ? g_xl : g_xh)
                + (((((size_t)kw * BB + b) * CIN + c) * HIN + oh + kh) << 7)
                + owbase + (acq << 3);
            cpa16(st + ahalf * 2048 + akr * 128 + ((acq ^ (akr & 7)) << 4), src);
        }
#pragma unroll
        for (int s = 0; s < 2; ++s) {   // B: 128 rows x 4 chunks = 512 ops
            const int idx = tid + (s << 8);
            const int n = idx >> 2, cq = idx & 3;
            const __nv_bfloat16* src = (cq < 2 ? g_ewh : g_ewl)
                + (size_t)(fbase + n) * KCONV + k0 + ((cq & 1) << 3);
            cpa16(st + SMB_BIG + n * 64 + ((cq ^ ((n >> 1) & 3)) << 4), src);
        }
    };
    auto maybe_issue = [&](int ch) {
        if (ch < K1_NCH) issue_stage(ch);
        CP_COMMIT();
    };

    float acc[2][4][4];
#pragma unroll
    for (int i = 0; i < 2; ++i)
#pragma unroll
        for (int j = 0; j < 4; ++j)
#pragma unroll
            for (int q = 0; q < 4; ++q) acc[i][j][q] = 0.f;

    maybe_issue(0); maybe_issue(1); maybe_issue(2); maybe_issue(3);

    for (int cc = 0; cc < K1_NCH; cc += 2) {
        CP_WAIT2();
        __syncthreads();
        maybe_issue(cc + 4); maybe_issue(cc + 5);

#pragma unroll
        for (int d = 0; d < 2; ++d) {
            const uint32_t st = sb + ((cc + d) % NSTAGE) * STG_BIG;
            uint32_t a0[4], a1[4];
            lda_t(a0, st, m0w, lane);
            lda_t(a1, st, m0w + 16, lane);
            mma_pass64(st + SMB_BIG, 0, a0, a1, n0w, lane, acc);   // Ah*Bh
            mma_pass64(st + SMB_BIG, 2, a0, a1, n0w, lane, acc);   // Ah*Bl
            lda_t(a0, st + 2048, m0w, lane);
            lda_t(a1, st + 2048, m0w + 16, lane);
            mma_pass64(st + SMB_BIG, 0, a0, a1, n0w, lane, acc);   // Al*Bh
        }
    }

    // epilogue: bias + relu, split hi/lo, write g_hh/g_hl [P][f]
    float ebv[8];
#pragma unroll
    for (int nj = 0; nj < 4; ++nj) {
        const int f = fbase + n0w + nj * 8 + (lane & 3) * 2;
        ebv[2 * nj]     = __ldg(&eb[f]);
        ebv[2 * nj + 1] = __ldg(&eb[f + 1]);
    }
#pragma unroll
    for (int mi = 0; mi < 2; ++mi) {
#pragma unroll
        for (int half = 0; half < 2; ++half) {
            const int ow = owbase + m0w + mi * 16 + half * 8 + (lane >> 2);
            if (ow < WO) {
                const size_t base = (size_t)((b * HO + oh) * WO + ow) * FS;
#pragma unroll
                for (int nj = 0; nj < 4; ++nj) {
                    const int f = fbase + n0w + nj * 8 + (lane & 3) * 2;
                    const float v0 = fmaxf(acc[mi][nj][half * 2 + 0] + ebv[2 * nj], 0.f);
                    const float v1 = fmaxf(acc[mi][nj][half * 2 + 1] + ebv[2 * nj + 1], 0.f);
                    __nv_bfloat16 h0, l0, h1, l1;
                    split2(v0, h0, l0); split2(v1, h1, l1);
                    const uint32_t ph = (uint32_t)__bfloat16_as_ushort(h0) |
                                        ((uint32_t)__bfloat16_as_ushort(h1) << 16);
                    const uint32_t pl = (uint32_t)__bfloat16_as_ushort(l0) |
                                        ((uint32_t)__bfloat16_as_ushort(l1) << 16);
                    *(uint32_t*)&g_hh[base + f] = ph;
                    *(uint32_t*)&g_hl[base + f] = pl;
                }
            }
        }
    }
}

// ---------------------------------------------------------------------------
// Kernel 2a: dec 1x1 GEMM, 1-pass (loss only).  CTA 64 pos x 128 cols.
// nt 0..4 covering cols 0..639 (cols >= 576 computed then discarded).
// ---------------------------------------------------------------------------
__global__ void __launch_bounds__(256, 3)
fc_dec_kernel(const float* __restrict__ x, const float* __restrict__ db)
{
    extern __shared__ uint8_t smem[];
    const uint32_t sb = smem_u32(smem);
    const int tid = threadIdx.x, lane = tid & 31, wid = tid >> 5;
    const int m0w = (wid >> 2) * 32, n0w = (wid & 3) * 32;
    const int nt = blockIdx.x, mt = blockIdx.y;
    const int P0 = mt * TM, N0 = nt * TN;

    auto issue_stage = [&](int ch) {
        const uint32_t st = sb + (ch % NSTAGE) * STG_SMALL;
        const int k0 = ch * KC;
        for (int i = tid; i < 384; i += 256) {
            if (i < 128) {                 // A: 64 rows x 2 chunks, hi only
                const int m = i >> 1, cq = i & 1;
                const __nv_bfloat16* src = g_hh + (size_t)(P0 + m) * FS + k0 + (cq << 3);
                cpa16(st + m * 32 + ((cq ^ ((m >> 2) & 1)) << 4), src);
            } else {                       // B: 128 rows x 2 chunks, hi only
                const int j = i - 128;
                const int n = j >> 1, cq = j & 1;
                const __nv_bfloat16* src = g_w2h + (size_t)(N0 + n) * FS + k0 + (cq << 3);
                cpa16(st + SMB_SMALL + n * 32 + ((cq ^ ((n >> 2) & 1)) << 4), src);
            }
        }
    };
    auto maybe_issue = [&](int ch) {
        if (ch < K2_NCH) issue_stage(ch);
        CP_COMMIT();
    };

    float acc[2][4][4];
#pragma unroll
    for (int i = 0; i < 2; ++i)
#pragma unroll
        for (int j = 0; j < 4; ++j)
#pragma unroll
            for (int q = 0; q < 4; ++q) acc[i][j][q] = 0.f;

    maybe_issue(0); maybe_issue(1); maybe_issue(2); maybe_issue(3);

    for (int cc = 0; cc < K2_NCH; cc += 2) {
        CP_WAIT2();
        __syncthreads();
        maybe_issue(cc + 4); maybe_issue(cc + 5);

#pragma unroll
        for (int d = 0; d < 2; ++d) {
            const uint32_t st = sb + ((cc + d) % NSTAGE) * STG_SMALL;
            uint32_t a0[4], a1[4];
            lda32(a0, st, m0w, lane);
            lda32(a1, st, m0w + 16, lane);
            mma_pass32(st + SMB_SMALL, a0, a1, n0w, lane, acc);
        }
    }

    // epilogue: sigmoid + MSE partials for dec cols only
    float lsum = 0.f;
#pragma unroll
    for (int mi = 0; mi < 2; ++mi) {
#pragma unroll
        for (int half = 0; half < 2; ++half) {
            const int m = m0w + mi * 16 + half * 8 + (lane >> 2);
            const int P = P0 + m;
            if (P < NPOS) {
                const int bb = P / (HO * WO);
                const int r2 = P - bb * (HO * WO);
                const int ohh = r2 / WO;
                const int oww = r2 - ohh * WO;
#pragma unroll
                for (int nj = 0; nj < 4; ++nj) {
#pragma unroll
                    for (int e = 0; e < 2; ++e) {
                        const int ng = N0 + n0w + nj * 8 + (lane & 3) * 2 + e;
                        if (ng < DEC) {
                            const int c = ng / 9, t = ng - c * 9;
                            const int kh = t / 3, kw = t - kh * 3;
                            const float z = acc[mi][nj][half * 2 + e] + __ldg(&db[ng]);
                            const float aux = 1.f / (1.f + expf(-z));
                            const float tg = x[(((size_t)bb * CIN + c) * HIN
                                               + ohh + kh) * WIN + oww + kw];
                            const float df = tg - aux;
                            lsum += df * df;
                        }
                    }
                }
            }
        }
    }

    __syncthreads();
    float* red_s = (float*)smem;
    red_s[tid] = lsum;
    __syncthreads();
#pragma unroll
    for (int s = 128; s > 0; s >>= 1) {
        if (tid < s) red_s[tid] += red_s[tid + s];
        __syncthreads();
    }
    if (tid == 0) g_part[mt * FC1_NT + nt] = red_s[0];
}

// ---------------------------------------------------------------------------
// Kernel 2b: red 1x1 GEMM, 3-pass (output).  Single n-tile at N0=576.
// ---------------------------------------------------------------------------
__global__ void __launch_bounds__(256, 3)
fc_red_kernel(const float* __restrict__ rb, float* __restrict__ out)
{
    extern __shared__ uint8_t smem[];
    const uint32_t sb = smem_u32(smem);
    const int tid = threadIdx.x, lane = tid & 31, wid = tid >> 5;
    const int m0w = (wid >> 2) * 32, n0w = (wid & 3) * 32;
    const int mt = blockIdx.y;
    const int P0 = mt * TM;
    const int N0 = RED_N0;

    auto issue_stage = [&](int ch) {
        const uint32_t st = sb + (ch % NSTAGE) * STG_BIG;
        const int k0 = ch * KC;
        {   // A: 64 rows x 4 chunks (hi/lo) = 256 ops
            const int m = tid >> 2, cq = tid & 3;
            const __nv_bfloat16* g = (cq < 2) ? g_hh : g_hl;
            const __nv_bfloat16* src = g + (size_t)(P0 + m) * FS + k0 + ((cq & 1) << 3);
            cpa16(st + m * 64 + ((cq ^ ((m >> 1) & 3)) << 4), src);
        }
#pragma unroll
        for (int s = 0; s < 2; ++s) {   // B: 128 rows x 4 chunks = 512 ops
            const int idx = tid + (s << 8);
            const int n = idx >> 2, cq = idx & 3;
            const __nv_bfloat16* g = (cq < 2) ? g_w2h : g_w2l;
            const __nv_bfloat16* src = g + (size_t)(N0 + n) * FS + k0 + ((cq & 1) << 3);
            cpa16(st + SMB_BIG + n * 64 + ((cq ^ ((n >> 1) & 3)) << 4), src);
        }
    };
    auto maybe_issue = [&](int ch) {
        if (ch < K2_NCH) issue_stage(ch);
        CP_COMMIT();
    };

    float acc[2][4][4];
#pragma unroll
    for (int i = 0; i < 2; ++i)
#pragma unroll
        for (int j = 0; j < 4; ++j)
#pragma unroll
            for (int q = 0; q < 4; ++q) acc[i][j][q] = 0.f;

    maybe_issue(0); maybe_issue(1); maybe_issue(2); maybe_issue(3);

    for (int cc = 0; cc < K2_NCH; cc += 2) {
        CP_WAIT2();
        __syncthreads();
        maybe_issue(cc + 4); maybe_issue(cc + 5);

#pragma unroll
        for (int d = 0; d < 2; ++d) {
            const uint32_t st = sb + ((cc + d) % NSTAGE) * STG_BIG;
            uint32_t a0[4], a1[4];
            lda64(a0, st, 0, m0w, lane);
            lda64(a1, st, 0, m0w + 16, lane);
            mma_pass64(st + SMB_BIG, 0, a0, a1, n0w, lane, acc);     // Ah*Bh
            mma_pass64(st + SMB_BIG, 2, a0, a1, n0w, lane, acc);     // Ah*Bl
            lda64(a0, st, 2, m0w, lane);
            lda64(a1, st, 2, m0w + 16, lane);
            mma_pass64(st + SMB_BIG, 0, a0, a1, n0w, lane, acc);     // Al*Bh
        }
    }

    // epilogue: bias + write out (all 128 cols are red outputs)
#pragma unroll
    for (int mi = 0; mi < 2; ++mi) {
#pragma unroll
        for (int half = 0; half < 2; ++half) {
            const int m = m0w + mi * 16 + half * 8 + (lane >> 2);
            const int P = P0 + m;
            if (P < NPOS) {
                const int bb = P / (HO * WO);
                const int r2 = P - bb * (HO * WO);
#pragma unroll
                for (int nj = 0; nj < 4; ++nj) {
#pragma unroll
                    for (int e = 0; e < 2; ++e) {
                        const int o = n0w + nj * 8 + (lane & 3) * 2 + e;
                        out[((size_t)bb * RED + o) * (HO * WO) + r2] =
                            acc[mi][nj][half * 2 + e] + __ldg(&rb[o]);
                    }
                }
            }
        }
    }
}

// ---------------------------------------------------------------------------
// Kernel 3: final loss scalar (deterministic double accumulation)
// ---------------------------------------------------------------------------
__global__ void loss_reduce_kernel(float* __restrict__ out, int scalar_idx)
{
    __shared__ double s[256];
    double v = 0.0;
    for (int i = threadIdx.x; i < LOSS_N; i += 256)
        v += (double)g_part[i];
    s[threadIdx.x] = v;
    __syncthreads();
#pragma unroll
    for (int st = 128; st > 0; st >>= 1) {
        if (threadIdx.x < st) s[threadIdx.x] += s[threadIdx.x + st];
        __syncthreads();
    }
    if (threadIdx.x == 0)
        out[scalar_idx] = (float)(s[0] / (double)((size_t)NPOS * DEC));
}

// ---------------------------------------------------------------------------
// Launch
// ---------------------------------------------------------------------------
extern "C" void kernel_launch(void* const* d_in, const int* in_sizes, int n_in,
                              void* d_out, int out_size)
{
    const float* x  = (const float*)d_in[0];
    const float* ew = (const float*)d_in[1];
    const float* eb = (const float*)d_in[2];
    const float* dw = (const float*)d_in[3];
    const float* db = (const float*)d_in[4];
    const float* rw = (const float*)d_in[5];
    const float* rb = (const float*)d_in[6];
    float* out = (float*)d_out;

    static bool attr_set = false;
    if (!attr_set) {
        cudaFuncSetAttribute(conv_mma_kernel,
                             cudaFuncAttributeMaxDynamicSharedMemorySize, SMEM_BIG);
        cudaFuncSetAttribute(fc_dec_kernel,
                             cudaFuncAttributeMaxDynamicSharedMemorySize, SMEM_SMALL);
        cudaFuncSetAttribute(fc_red_kernel,
                             cudaFuncAttributeMaxDynamicSharedMemorySize, SMEM_BIG);
        attr_set = true;
    }

    {   // pre-split inputs to bf16 hi/lo
        const size_t nx = (size_t)3 * BB * CIN * HIN * WPAD;
        prep_x_kernel<<<(unsigned)((nx + 511) / 512), 512>>>(x);
        const int nw = FS * KCONV + NV * FS;
        prep_w_kernel<<<(nw + 511) / 512, 512>>>(ew, dw, rw);
    }
    {   // conv3x3 -> H (bf16 hi/lo)
        dim3 grid(8, BB * HO);                       // (4 ftiles x 2 mhalf, 880)
        conv_mma_kernel<<<grid, 256, SMEM_BIG>>>(eb);
    }
    {   // fc: 5 dec 1-pass tiles + 1 red 3-pass tile
        dim3 grid_a(FC1_NT, K2_MT);
        fc_dec_kernel<<<grid_a, 256, SMEM_SMALL>>>(x, db);
        dim3 grid_b(1, K2_MT);
        fc_red_kernel<<<grid_b, 256, SMEM_BIG>>>(rb, out);
    }
    loss_reduce_kernel<<<1, 256>>>(out, out_size - 1);
}